// round 5
// baseline (speedup 1.0000x reference)
#include <cuda_runtime.h>
#include <math.h>

#define H    1024
#define NA   128
#define OP   16
#define G    32
#define NB   128          // blocks (co-resident on 148+ SMs)
#define NT   512          // 16 warps/block; 2 warps per hidden unit; 8 units/block
#define ACCB 1            // block owning scalar softmax accumulation

typedef unsigned long long ull;

#define QSCALE  327670.0f          // |w| < 0.1  ->  |q| <= 32767
#define QINV    (1.0f / 327670.0f)
#define DEC_BIAS (-8421376.0f)     // -(8388608 + 32768)

// ---------------- persistent device state (no allocations allowed) ----------------
__device__ __align__(16) float g_h[2][2][2][H];   // [parity][substep][layer][j]
__device__ __align__(16) float g_c[2][2][2][H];
__device__ float g_ctx_logits[OP];
__device__ float g_left_logits[G];
__device__ float g_ent, g_lp;
__device__ volatile unsigned g_flags[NB];         // all-to-all barrier flags

// biased-u16 weight scratch (filled by prep kernel every launch) + fused biases
__device__ __align__(32) unsigned short g_Wih_q[2u * 4u * H * H];   // 16.8 MB
__device__ __align__(32) unsigned short g_Whh_q[2u * 4u * H * H];   // 16.8 MB
__device__ __align__(16) float g_bsum[2 * 4 * H];

// ---------------- packed f32x2 helpers -------------------------------------------
__device__ __forceinline__ void fma2(ull& a, ull b, ull c) {
    asm("fma.rn.f32x2 %0, %1, %2, %0;" : "+l"(a) : "l"(b), "l"(c));
}
__device__ __forceinline__ ull pack2(float x, float y) {
    ull v; asm("mov.b64 %0, {%1, %2};" : "=l"(v) : "f"(x), "f"(y)); return v;
}
__device__ __forceinline__ float2 unpack2(ull v) {
    float2 f; asm("mov.b64 {%0, %1}, %2;" : "=f"(f.x), "=f"(f.y) : "l"(v)); return f;
}
// exact biased-u16 pair -> f32x2 of the original int16 values (no cvt instructions):
// PRMT splices each u16 into the mantissa of 2^23 (0x4B000000) => f32 = 8388608+u,
// then one packed add of -8421376 gives (u - 32768) exactly.
__device__ __forceinline__ ull dec2(unsigned w, unsigned magic, ull bias2) {
    unsigned lo, hi;
    asm("prmt.b32 %0, %1, %2, 0x7410;" : "=r"(lo) : "r"(w), "r"(magic));
    asm("prmt.b32 %0, %1, %2, 0x7432;" : "=r"(hi) : "r"(w), "r"(magic));
    ull v;
    asm("mov.b64 %0, {%1, %2};" : "=l"(v) : "r"(lo), "r"(hi));
    asm("add.rn.f32x2 %0, %0, %1;" : "+l"(v) : "l"(bias2));
    return v;
}

// 32-byte weight load pinned to L2 (evict_last requires .v4.b64 on sm_103a)
struct U8w { unsigned u[8]; };
__device__ __forceinline__ U8w ldg_el32(const void* p) {
    ull r0, r1, r2, r3;
    asm("ld.global.nc.L2::evict_last.v4.b64 {%0,%1,%2,%3}, [%4];"
        : "=l"(r0), "=l"(r1), "=l"(r2), "=l"(r3) : "l"(p));
    U8w v;
    asm("mov.b64 {%0,%1}, %2;" : "=r"(v.u[0]), "=r"(v.u[1]) : "l"(r0));
    asm("mov.b64 {%0,%1}, %2;" : "=r"(v.u[2]), "=r"(v.u[3]) : "l"(r1));
    asm("mov.b64 {%0,%1}, %2;" : "=r"(v.u[4]), "=r"(v.u[5]) : "l"(r2));
    asm("mov.b64 {%0,%1}, %2;" : "=r"(v.u[6]), "=r"(v.u[7]) : "l"(r3));
    return v;
}

__device__ __forceinline__ float warp_reduce(float v) {
#pragma unroll
    for (int o = 16; o; o >>= 1) v += __shfl_xor_sync(0xffffffffu, v, o);
    return v;
}
__device__ __forceinline__ float dot4(float4 a, float4 b) {
    return a.x * b.x + a.y * b.y + a.z * b.z + a.w * b.w;
}

// ---------------- all-to-all grid barrier (flag per block, replay-safe) -----------
__device__ __forceinline__ void grid_barrier(unsigned target, int lane) {
    __threadfence();
    __syncthreads();
    if (threadIdx.x == 0) g_flags[blockIdx.x] = target;
    if (threadIdx.x < 32) {
        for (;;) {
            unsigned f0 = g_flags[lane];
            unsigned f1 = g_flags[lane + 32];
            unsigned f2 = g_flags[lane + 64];
            unsigned f3 = g_flags[lane + 96];
            bool ok = ((int)(f0 - target) >= 0) && ((int)(f1 - target) >= 0) &&
                      ((int)(f2 - target) >= 0) && ((int)(f3 - target) >= 0);
            if (__all_sync(0xffffffffu, ok)) break;
        }
        __threadfence();
    }
    __syncthreads();
}

// stage 1024 floats into SMEM with 512 threads (1 float2 each)
__device__ __forceinline__ void stage_vec(float* dst, const float* src) {
    ((float2*)dst)[threadIdx.x] = ((const float2*)src)[threadIdx.x];
}
__device__ __forceinline__ void stage_zero(float* dst) {
    ((float2*)dst)[threadIdx.x] = make_float2(0.f, 0.f);
}

// per-warp LSTM half-row partial: warp covers 512 columns (half = 0/1) of all
// 8 gate rows of unit j. Returns 4 combined (ih+hh) partial dots (valid all lanes).
__device__ __forceinline__ void lstm_partial(
    int j, int lane, int half,
    const unsigned short* __restrict__ Wih, const unsigned short* __restrict__ Whh,
    const float* x_s, const float* h_s,
    float p[4])
{
    const unsigned magic = 0x4B000000u;
    const ull bias2 = pack2(DEC_BIAS, DEC_BIAS);
    const size_t coloff = (size_t)half * 512 + (size_t)lane * 16;  // element offset

    ull acc[8] = {0, 0, 0, 0, 0, 0, 0, 0};

    // ---- group A: 4 ih rows against x ----
    {
        const float4* xv = (const float4*)x_s + (half * 128 + lane * 4);
        ull xq[8];
#pragma unroll
        for (int k = 0; k < 4; ++k) {
            float4 v = xv[k];
            xq[2 * k]     = pack2(v.x, v.y);
            xq[2 * k + 1] = pack2(v.z, v.w);
        }
        U8w w[4];
#pragma unroll
        for (int r = 0; r < 4; ++r)
            w[r] = ldg_el32(Wih + ((size_t)r * H + j) * H + coloff);
#pragma unroll
        for (int r = 0; r < 4; ++r)
#pragma unroll
            for (int k = 0; k < 8; ++k)
                fma2(acc[r], dec2(w[r].u[k], magic, bias2), xq[k]);
    }
    // ---- group B: 4 hh rows against h ----
    {
        const float4* hv = (const float4*)h_s + (half * 128 + lane * 4);
        ull hq[8];
#pragma unroll
        for (int k = 0; k < 4; ++k) {
            float4 v = hv[k];
            hq[2 * k]     = pack2(v.x, v.y);
            hq[2 * k + 1] = pack2(v.z, v.w);
        }
        U8w w[4];
#pragma unroll
        for (int r = 0; r < 4; ++r)
            w[r] = ldg_el32(Whh + ((size_t)r * H + j) * H + coloff);
#pragma unroll
        for (int r = 0; r < 4; ++r)
#pragma unroll
            for (int k = 0; k < 8; ++k)
                fma2(acc[4 + r], dec2(w[r].u[k], magic, bias2), hq[k]);
    }

#pragma unroll
    for (int g = 0; g < 4; ++g) {
        float2 a = unpack2(acc[g]);
        float2 b = unpack2(acc[g + 4]);
        p[g] = warp_reduce((a.x + a.y) + (b.x + b.y));
    }
}

// head row dot: fp32 weight row (global, streaming) . x (SMEM or global)
__device__ __forceinline__ float head_dot(const float* __restrict__ w,
                                          const float* x, int lane) {
    const float4* wv = (const float4*)w;
    const float4* xv = (const float4*)x;
    float a = 0.f;
#pragma unroll
    for (int it = 0; it < 8; ++it) {
        int t = it * 32 + lane;
        a += dot4(__ldcs(wv + t), xv[t]);
    }
    return warp_reduce(a);
}

// single-thread log-softmax + entropy/log-prob accumulation (deterministic)
__device__ __forceinline__ void acc_softmax(const float* logits, int n,
                                            int chosen, float mask) {
    float m = -1e30f;
    for (int i = 0; i < n; ++i) m = fmaxf(m, logits[i]);
    float se = 0.f;
    for (int i = 0; i < n; ++i) se += expf(logits[i] - m);
    float lse = m + logf(se);
    float s = 0.f;
    for (int i = 0; i < n; ++i) { float ls = logits[i] - lse; s += expf(ls) * ls; }
    g_ent += mask * (-s);
    g_lp  += mask * (logits[chosen] - lse);
}

// ---------------- prep kernels (run every launch; deterministic) ------------------
__global__ void __launch_bounds__(256)
convert_kernel(const float* __restrict__ Wih, const float* __restrict__ Whh) {
    const size_t N4 = (size_t)2 * 4 * H * H / 4;   // float4 count per tensor
    size_t i = (size_t)blockIdx.x * blockDim.x + threadIdx.x;
    float4 v;
    ushort4* dst;
    if (i < N4) {
        v   = __ldcs((const float4*)Wih + i);      // streaming: don't pollute L2
        dst = (ushort4*)(g_Wih_q + i * 4);
    } else {
        size_t k = i - N4;
        v   = __ldcs((const float4*)Whh + k);
        dst = (ushort4*)(g_Whh_q + k * 4);
    }
    ushort4 q;
    q.x = (unsigned short)(__float2int_rn(v.x * QSCALE) + 32768);
    q.y = (unsigned short)(__float2int_rn(v.y * QSCALE) + 32768);
    q.z = (unsigned short)(__float2int_rn(v.z * QSCALE) + 32768);
    q.w = (unsigned short)(__float2int_rn(v.w * QSCALE) + 32768);
    *dst = q;
}

__global__ void __launch_bounds__(256)
bias_kernel(const float* __restrict__ bih, const float* __restrict__ bhh) {
    int i = blockIdx.x * blockDim.x + threadIdx.x;   // 0..8191
    g_bsum[i] = bih[i] + bhh[i];
}

// ---------------- main persistent kernel ------------------------------------------
__global__ void __launch_bounds__(NT, 1)
controller_kernel(const float* __restrict__ g_emb,
                  const float* __restrict__ ctx_W, const float* __restrict__ ctx_b,
                  const float* __restrict__ left_W, const float* __restrict__ left_b,
                  const int* __restrict__ config, const int* __restrict__ left_config,
                  float* __restrict__ out)
{
    __shared__ __align__(16) float x_s[H];
    __shared__ __align__(16) float h_s[H];
    __shared__ float s_part[NT / 32][4];
    __shared__ unsigned s_base;

    const int tid  = threadIdx.x;
    const int lane = tid & 31;
    const int wid  = tid >> 5;                        // 0..15
    const int half = wid & 1;
    const int j    = blockIdx.x * 8 + (wid >> 1);     // hidden unit of this warp pair

    const bool leftw = ((blockIdx.x & 3) == 0) && (wid == 0);  // 32 left-head warps
    const int  leftr = blockIdx.x >> 2;
    const bool ctxw  = ((blockIdx.x & 7) == 0) && (wid == 0);  // 16 ctx-head warps
    const int  ctxr  = blockIdx.x >> 3;
    const bool accT  = (blockIdx.x == ACCB) && (tid == 0);

    if (tid == 0) s_base = g_flags[blockIdx.x];       // replay-safe barrier epoch base
    if (accT) { g_ent = 0.f; g_lp = 0.f; }
    __syncthreads();
    unsigned bar = s_base;

    const unsigned short* Wih0 = g_Wih_q;
    const unsigned short* Wih1 = g_Wih_q + (size_t)4 * H * H;
    const unsigned short* Whh0 = g_Whh_q;
    const unsigned short* Whh1 = g_Whh_q + (size_t)4 * H * H;
    const float* bs0 = g_bsum;
    const float* bs1 = g_bsum + 4 * H;

#define FINALIZE(BS, CPRE, ZEROC, HOUT, COUT)                                   \
    do {                                                                        \
        __syncthreads();                                                        \
        if (half == 0 && lane == 0) {                                           \
            float zi = (s_part[wid][0] + s_part[wid + 1][0]) * QINV + (BS)[0 * H + j]; \
            float zf = (s_part[wid][1] + s_part[wid + 1][1]) * QINV + (BS)[1 * H + j]; \
            float zg = (s_part[wid][2] + s_part[wid + 1][2]) * QINV + (BS)[2 * H + j]; \
            float zo = (s_part[wid][3] + s_part[wid + 1][3]) * QINV + (BS)[3 * H + j]; \
            float ii = 1.f / (1.f + expf(-zi));                                 \
            float ff = 1.f / (1.f + expf(-zf));                                 \
            float gg = tanhf(zg);                                               \
            float oo = 1.f / (1.f + expf(-zo));                                 \
            float cp = (ZEROC) ? 0.f : (CPRE)[j];                               \
            float cn = ff * cp + ii * gg;                                       \
            (COUT)[j] = cn;                                                     \
            (HOUT)[j] = oo * tanhf(cn);                                         \
        }                                                                       \
    } while (0)

    for (int a = 0; a < NA; ++a) {
        const int  q     = a & 1;
        const int  p     = q ^ 1;
        const bool first = (a == 0);
        const int  sel   = (!first && config[a - 1] == 1) ? 1 : 0;
        float prt[4];

        // ---- PHASE A: substep 0, layer 0 (+ left-head dots for step a-1) ----------
        stage_vec(x_s, first ? g_emb : g_h[p][sel][1]);
        if (first) stage_zero(h_s); else stage_vec(h_s, g_h[p][sel][0]);
        __syncthreads();
        lstm_partial(j, lane, half, Wih0, Whh0, x_s, h_s, prt);
        if (lane == 0) { s_part[wid][0]=prt[0]; s_part[wid][1]=prt[1];
                         s_part[wid][2]=prt[2]; s_part[wid][3]=prt[3]; }
        if (!first && leftw) {
            float d = head_dot(left_W + ((size_t)(a - 1) * G + leftr) * H,
                               g_h[p][1][1], lane);
            if (lane == 0) g_left_logits[leftr] = d + left_b[(a - 1) * G + leftr];
        }
        FINALIZE(bs0, g_c[p][sel][0], first, g_h[q][0][0], g_c[q][0][0]);
        grid_barrier(++bar, lane);

        // ---- PHASE B: substep 0, layer 1 (+ left-head reduce for a-1) -------------
        stage_vec(x_s, g_h[q][0][0]);
        if (first) stage_zero(h_s); else stage_vec(h_s, g_h[p][sel][1]);
        __syncthreads();
        lstm_partial(j, lane, half, Wih1, Whh1, x_s, h_s, prt);
        if (lane == 0) { s_part[wid][0]=prt[0]; s_part[wid][1]=prt[1];
                         s_part[wid][2]=prt[2]; s_part[wid][3]=prt[3]; }
        if (!first && accT)
            acc_softmax(g_left_logits, G, left_config[a - 1],
                        (config[a - 1] == 1) ? 1.f : 0.f);
        FINALIZE(bs1, g_c[p][sel][1], first, g_h[q][0][1], g_c[q][0][1]);
        grid_barrier(++bar, lane);

        // ---- PHASE C: substep 1 (gap), layer 0 (+ ctx-head dots; x_s == out1) -----
        stage_vec(x_s, g_h[q][0][1]);
        stage_vec(h_s, g_h[q][0][0]);
        __syncthreads();
        lstm_partial(j, lane, half, Wih0, Whh0, x_s, h_s, prt);
        if (lane == 0) { s_part[wid][0]=prt[0]; s_part[wid][1]=prt[1];
                         s_part[wid][2]=prt[2]; s_part[wid][3]=prt[3]; }
        if (ctxw) {
            float d = head_dot(ctx_W + ((size_t)a * OP + ctxr) * H, x_s, lane);
            if (lane == 0) g_ctx_logits[ctxr] = d + ctx_b[a * OP + ctxr];
        }
        FINALIZE(bs0, g_c[q][0][0], false, g_h[q][1][0], g_c[q][1][0]);
        grid_barrier(++bar, lane);

        // ---- PHASE D: substep 1 (gap), layer 1 (+ ctx-head reduce) ----------------
        stage_vec(x_s, g_h[q][1][0]);
        stage_vec(h_s, g_h[q][0][1]);
        __syncthreads();
        lstm_partial(j, lane, half, Wih1, Whh1, x_s, h_s, prt);
        if (lane == 0) { s_part[wid][0]=prt[0]; s_part[wid][1]=prt[1];
                         s_part[wid][2]=prt[2]; s_part[wid][3]=prt[3]; }
        if (accT)
            acc_softmax(g_ctx_logits, OP, config[a], 1.f);
        FINALIZE(bs1, g_c[q][0][1], false, g_h[q][1][1], g_c[q][1][1]);
        grid_barrier(++bar, lane);
    }

    // ---- epilogue: left head for final step (a = 127, parity 1) -------------------
    if (leftw) {
        float d = head_dot(left_W + ((size_t)(NA - 1) * G + leftr) * H,
                           g_h[1][1][1], lane);
        if (lane == 0) g_left_logits[leftr] = d + left_b[(NA - 1) * G + leftr];
    }
    grid_barrier(++bar, lane);
    if (accT) {
        acc_softmax(g_left_logits, G, left_config[NA - 1],
                    (config[NA - 1] == 1) ? 1.f : 0.f);
        out[0] = g_ent;
        out[1] = g_lp;
    }
#undef FINALIZE
}

extern "C" void kernel_launch(void* const* d_in, const int* in_sizes, int n_in,
                              void* d_out, int out_size) {
    (void)in_sizes; (void)n_in; (void)out_size;
    const float* g_emb_p    = (const float*)d_in[0];
    const float* W_ih_p     = (const float*)d_in[1];
    const float* W_hh_p     = (const float*)d_in[2];
    const float* b_ih_p     = (const float*)d_in[3];
    const float* b_hh_p     = (const float*)d_in[4];
    const float* ctx_W_p    = (const float*)d_in[5];
    const float* ctx_b_p    = (const float*)d_in[6];
    const float* left_W_p   = (const float*)d_in[7];
    const float* left_b_p   = (const float*)d_in[8];
    const int*   config_p   = (const int*)d_in[9];
    const int*   left_cfg_p = (const int*)d_in[10];
    float* out = (float*)d_out;

    // biased-u16 weight conversion: 2 tensors x (2*4*H*H/4) float4 threads
    const size_t N4 = (size_t)2 * 4 * H * H / 4;           // 2,097,152 per tensor
    const int conv_blocks = (int)((2 * N4 + 255) / 256);   // 16384
    convert_kernel<<<conv_blocks, 256>>>(W_ih_p, W_hh_p);
    bias_kernel<<<(2 * 4 * H) / 256, 256>>>(b_ih_p, b_hh_p);

    controller_kernel<<<NB, NT>>>(g_emb_p, ctx_W_p, ctx_b_p, left_W_p, left_b_p,
                                  config_p, left_cfg_p, out);
}

// round 6
// speedup vs baseline: 1.3859x; 1.3859x over previous
#include <cuda_runtime.h>
#include <math.h>

#define H    1024
#define NA   128
#define OP   16
#define G    32
#define UPB  7            // hidden units per block
#define NB   147          // 147*7 = 1029 >= 1024; all co-resident (<=148 SMs)
#define NT   480          // 15 warps: 14 compute (2 per unit) + 1 head warp
#define NW   15

typedef unsigned long long ull;

#define QSCALE   327670.0f         // |w| < 0.1 -> |q| <= 32767
#define QINV     (1.0f / 327670.0f)
#define DEC_BIAS (-8421376.0f)     // -(8388608 + 32768)

#define LAYER_STRIDE (UPB * 2 * 4 * H)          // u16 elements per layer per block
#define SMEM_DYN     (2 * LAYER_STRIDE * 2)     // bytes: 229376

// ---------------- persistent device state (no allocations allowed) ----------------
__device__ __align__(16) float g_h[2][2][2][H];   // [parity][substep][layer][j]
__device__ __align__(16) float g_c[2][2][2][H];
__device__ float g_ctx_logits[OP];
__device__ float g_left_logits[G];
__device__ float g_ent, g_lp;
__device__ volatile unsigned g_flags[160];        // all-to-all barrier flags (padded)

// ---------------- packed f32x2 helpers -------------------------------------------
__device__ __forceinline__ void fma2(ull& a, ull b, ull c) {
    asm("fma.rn.f32x2 %0, %1, %2, %0;" : "+l"(a) : "l"(b), "l"(c));
}
__device__ __forceinline__ ull pack2(float x, float y) {
    ull v; asm("mov.b64 %0, {%1, %2};" : "=l"(v) : "f"(x), "f"(y)); return v;
}
__device__ __forceinline__ float2 unpack2(ull v) {
    float2 f; asm("mov.b64 {%0, %1}, %2;" : "=f"(f.x), "=f"(f.y) : "l"(v)); return f;
}
// exact biased-u16 pair -> f32x2 of original int16 values (PRMT splice, no cvt)
__device__ __forceinline__ ull dec2(unsigned w, unsigned magic, ull bias2) {
    unsigned lo, hi;
    asm("prmt.b32 %0, %1, %2, 0x7410;" : "=r"(lo) : "r"(w), "r"(magic));
    asm("prmt.b32 %0, %1, %2, 0x7432;" : "=r"(hi) : "r"(w), "r"(magic));
    ull v;
    asm("mov.b64 %0, {%1, %2};" : "=l"(v) : "r"(lo), "r"(hi));
    asm("add.rn.f32x2 %0, %0, %1;" : "+l"(v) : "l"(bias2));
    return v;
}

__device__ __forceinline__ float warp_reduce(float v) {
#pragma unroll
    for (int o = 16; o; o >>= 1) v += __shfl_xor_sync(0xffffffffu, v, o);
    return v;
}
__device__ __forceinline__ float dot4(float4 a, float4 b) {
    return a.x * b.x + a.y * b.y + a.z * b.z + a.w * b.w;
}

// ---------------- all-to-all grid barrier (flag per block, replay-safe) -----------
__device__ __forceinline__ void grid_barrier(unsigned target, int lane) {
    __threadfence();
    __syncthreads();
    if (threadIdx.x == 0) g_flags[blockIdx.x] = target;
    if (threadIdx.x < 32) {
        for (;;) {
            bool ok = true;
#pragma unroll
            for (int k = 0; k < 5; ++k) {
                int idx = k * 32 + lane;
                unsigned f = g_flags[idx];
                ok &= (idx >= NB) | ((int)(f - target) >= 0);
            }
            if (__all_sync(0xffffffffu, ok)) break;
        }
        __threadfence();   // flushes L1 -> fresh view of other blocks' h/c stores
    }
    __syncthreads();
}

// per-warp partial: 4 gate rows (u16, SMEM) . vec (fp32, global), 1024 cols.
// Conflict-free: lane-consecutive 16B chunks. Result valid on all lanes.
__device__ __forceinline__ void lstm_partial(
    const unsigned short* wbase,            // SMEM: [4][1024] u16 rows
    const float* __restrict__ vec,          // global: 1024 floats
    int lane, float p[4])
{
    const unsigned magic = 0x4B000000u;
    const ull bias2 = pack2(DEC_BIAS, DEC_BIAS);
    ull acc[4] = {0, 0, 0, 0};

#pragma unroll
    for (int k = 0; k < 4; ++k) {
        const int c16 = k * 32 + lane;                  // 16B chunk id (0..127)
        const float4* vp = (const float4*)vec + c16 * 2;
        float4 va = vp[0], vb = vp[1];                  // 8 cols of vec
        ull v0 = pack2(va.x, va.y), v1 = pack2(va.z, va.w);
        ull v2 = pack2(vb.x, vb.y), v3 = pack2(vb.z, vb.w);
#pragma unroll
        for (int r = 0; r < 4; ++r) {
            uint4 w = ((const uint4*)(wbase + r * H))[c16];   // LDS.128
            fma2(acc[r], dec2(w.x, magic, bias2), v0);
            fma2(acc[r], dec2(w.y, magic, bias2), v1);
            fma2(acc[r], dec2(w.z, magic, bias2), v2);
            fma2(acc[r], dec2(w.w, magic, bias2), v3);
        }
    }
#pragma unroll
    for (int g = 0; g < 4; ++g) {
        float2 s = unpack2(acc[g]);
        p[g] = warp_reduce(s.x + s.y);
    }
}

// head row dot: fp32 weight row (global, streaming) . x (global)
__device__ __forceinline__ float head_dot(const float* __restrict__ w,
                                          const float* __restrict__ x, int lane) {
    const float4* wv = (const float4*)w;
    const float4* xv = (const float4*)x;
    float a = 0.f;
#pragma unroll
    for (int it = 0; it < 8; ++it) {
        int t = it * 32 + lane;
        a += dot4(__ldcs(wv + t), xv[t]);
    }
    return warp_reduce(a);
}

// single-thread log-softmax + entropy/log-prob accumulation (deterministic)
__device__ __forceinline__ void acc_softmax(const float* logits, int n,
                                            int chosen, float mask) {
    float m = -1e30f;
    for (int i = 0; i < n; ++i) m = fmaxf(m, logits[i]);
    float se = 0.f;
    for (int i = 0; i < n; ++i) se += expf(logits[i] - m);
    float lse = m + logf(se);
    float s = 0.f;
    for (int i = 0; i < n; ++i) { float ls = logits[i] - lse; s += expf(ls) * ls; }
    g_ent += mask * (-s);
    g_lp  += mask * (logits[chosen] - lse);
}

// ---------------- the single persistent kernel ------------------------------------
__global__ void __launch_bounds__(NT, 1)
controller_kernel(const float* __restrict__ g_emb,
                  const float* __restrict__ W_ih, const float* __restrict__ W_hh,
                  const float* __restrict__ b_ih, const float* __restrict__ b_hh,
                  const float* __restrict__ ctx_W, const float* __restrict__ ctx_b,
                  const float* __restrict__ left_W, const float* __restrict__ left_b,
                  const int* __restrict__ config, const int* __restrict__ left_config,
                  float* __restrict__ out)
{
    extern __shared__ unsigned short w_s[];           // [2][UPB][2][4][H] u16
    __shared__ float s_part[NW][4];
    __shared__ int   s_cfg[NA], s_lcfg[NA];
    __shared__ unsigned s_base;

    const int tid  = threadIdx.x;
    const int lane = tid & 31;
    const int wid  = tid >> 5;                         // 0..14
    const int bid  = blockIdx.x;
    const int u    = wid >> 1;                         // unit within block (compute warps)
    const int m    = wid & 1;                          // 0 = ih (x), 1 = hh (h)
    const int j    = bid * UPB + u;
    const bool active = (wid < 14) && (j < H);

    const bool leftw = (wid == 14) && ((bid & 3) == 0) && ((bid >> 2) < G);
    const int  leftr = bid >> 2;
    const bool ctxw  = (wid == 14) && ((bid & 7) == 0) && ((bid >> 3) < OP);
    const int  ctxr  = bid >> 3;
    const bool accT  = (bid == 1) && (wid == 14) && (lane == 0);

    // ---------------- prologue: fill SMEM weights (quantize fp32 -> biased u16) ----
    if (tid == 0) s_base = g_flags[bid];
    if (accT) { g_ent = 0.f; g_lp = 0.f; }
    if (tid < NA) { s_cfg[tid] = config[tid]; s_lcfg[tid] = left_config[tid]; }

    for (int idx = tid; idx < 2 * UPB * 2 * 4 * (H / 4); idx += NT) {
        int col = (idx & 255) * 4;                 // 256 float4 per row
        int t   = idx >> 8;
        int r   = t & 3;  t >>= 2;
        int mm  = t & 1;  t >>= 1;
        int k   = t % UPB;
        int l   = t / UPB;
        int jj  = bid * UPB + k;
        if (jj < H) {
            const float* src = (mm ? W_hh : W_ih) +
                               (size_t)l * 4 * H * H + ((size_t)r * H + jj) * H + col;
            float4 v = __ldcs((const float4*)src);
            ushort4 q;
            q.x = (unsigned short)(__float2int_rn(v.x * QSCALE) + 32768);
            q.y = (unsigned short)(__float2int_rn(v.y * QSCALE) + 32768);
            q.z = (unsigned short)(__float2int_rn(v.z * QSCALE) + 32768);
            q.w = (unsigned short)(__float2int_rn(v.w * QSCALE) + 32768);
            *(ushort4*)(w_s + ((((size_t)l * UPB + k) * 2 + mm) * 4 + r) * H + col) = q;
        }
    }

    // per-finalize-thread bias registers: bsr[l*4+g]
    const int jt = bid * UPB + tid;                    // unit for finalize thread tid<UPB
    const bool jt_ok = (tid < UPB) && (jt < H);
    float bsr[8];
    if (jt_ok) {
#pragma unroll
        for (int l = 0; l < 2; ++l)
#pragma unroll
            for (int g = 0; g < 4; ++g)
                bsr[l * 4 + g] = b_ih[l * 4 * H + g * H + jt] + b_hh[l * 4 * H + g * H + jt];
    }
    __syncthreads();
    unsigned bar = s_base;

    const unsigned short* wb0 = w_s + ((size_t)u * 2 + m) * 4 * H;       // layer 0
    const unsigned short* wb1 = wb0 + LAYER_STRIDE;                      // layer 1

#define DO_PHASE(WB, XV, HV, ZERO_H, CPRE, ZERO_C, HOUT, COUT, LIDX)            \
    do {                                                                        \
        float cpre_r = 0.f;                                                     \
        if (jt_ok && !(ZERO_C)) cpre_r = (CPRE)[jt];                            \
        if (active) {                                                           \
            float prt[4];                                                       \
            if (m == 0)            lstm_partial((WB), (XV), lane, prt);         \
            else if (ZERO_H)       { prt[0]=prt[1]=prt[2]=prt[3]=0.f; }         \
            else                   lstm_partial((WB), (HV), lane, prt);         \
            if (lane == 0) { s_part[wid][0]=prt[0]; s_part[wid][1]=prt[1];      \
                             s_part[wid][2]=prt[2]; s_part[wid][3]=prt[3]; }    \
        }                                                                       \
        HEADCODE;                                                               \
        __syncthreads();                                                        \
        if (jt_ok) {                                                            \
            float zi = (s_part[2*tid][0]+s_part[2*tid+1][0])*QINV + bsr[(LIDX)*4+0]; \
            float zf = (s_part[2*tid][1]+s_part[2*tid+1][1])*QINV + bsr[(LIDX)*4+1]; \
            float zg = (s_part[2*tid][2]+s_part[2*tid+1][2])*QINV + bsr[(LIDX)*4+2]; \
            float zo = (s_part[2*tid][3]+s_part[2*tid+1][3])*QINV + bsr[(LIDX)*4+3]; \
            float ii = 1.f/(1.f+expf(-zi));                                     \
            float ff = 1.f/(1.f+expf(-zf));                                     \
            float gg = tanhf(zg);                                               \
            float oo = 1.f/(1.f+expf(-zo));                                     \
            float cn = ff*cpre_r + ii*gg;                                       \
            (COUT)[jt] = cn;                                                    \
            (HOUT)[jt] = oo*tanhf(cn);                                          \
        }                                                                       \
        grid_barrier(++bar, lane);                                              \
    } while (0)

    for (int a = 0; a < NA; ++a) {
        const int  q     = a & 1;
        const int  p     = q ^ 1;
        const bool first = (a == 0);
        const int  sel   = (!first && s_cfg[a - 1] == 1) ? 1 : 0;

        // ---- PHASE A: substep 0, layer 0; head warp: left dots for step a-1 -------
#define HEADCODE                                                                \
        if (!first && leftw) {                                                  \
            float d = head_dot(left_W + ((size_t)(a - 1) * G + leftr) * H,      \
                               g_h[p][1][1], lane);                             \
            if (lane == 0) g_left_logits[leftr] = d + left_b[(a - 1) * G + leftr]; \
        }
        DO_PHASE(wb0, (first ? g_emb : g_h[p][sel][1]), g_h[p][sel][0], first,
                 g_c[p][sel][0], first, g_h[q][0][0], g_c[q][0][0], 0);
#undef HEADCODE

        // ---- PHASE B: substep 0, layer 1; acc thread: left softmax for a-1 --------
#define HEADCODE                                                                \
        if (!first && accT)                                                     \
            acc_softmax(g_left_logits, G, s_lcfg[a - 1],                        \
                        (s_cfg[a - 1] == 1) ? 1.f : 0.f)
        DO_PHASE(wb1, g_h[q][0][0], g_h[p][sel][1], first,
                 g_c[p][sel][1], first, g_h[q][0][1], g_c[q][0][1], 1);
#undef HEADCODE

        // ---- PHASE C: substep 1 (gap), layer 0; head warp: ctx dots ---------------
#define HEADCODE                                                                \
        if (ctxw) {                                                             \
            float d = head_dot(ctx_W + ((size_t)a * OP + ctxr) * H,             \
                               g_h[q][0][1], lane);                             \
            if (lane == 0) g_ctx_logits[ctxr] = d + ctx_b[a * OP + ctxr];       \
        }
        DO_PHASE(wb0, g_h[q][0][1], g_h[q][0][0], false,
                 g_c[q][0][0], false, g_h[q][1][0], g_c[q][1][0], 0);
#undef HEADCODE

        // ---- PHASE D: substep 1 (gap), layer 1; acc thread: ctx softmax -----------
#define HEADCODE                                                                \
        if (accT) acc_softmax(g_ctx_logits, OP, s_cfg[a], 1.f)
        DO_PHASE(wb1, g_h[q][1][0], g_h[q][0][1], false,
                 g_c[q][0][1], false, g_h[q][1][1], g_c[q][1][1], 1);
#undef HEADCODE
    }

    // ---- epilogue: left head for final step (a = 127, parity 1) -------------------
    if (leftw) {
        float d = head_dot(left_W + ((size_t)(NA - 1) * G + leftr) * H,
                           g_h[1][1][1], lane);
        if (lane == 0) g_left_logits[leftr] = d + left_b[(NA - 1) * G + leftr];
    }
    grid_barrier(++bar, lane);
    if (accT) {
        acc_softmax(g_left_logits, G, s_lcfg[NA - 1],
                    (s_cfg[NA - 1] == 1) ? 1.f : 0.f);
        out[0] = g_ent;
        out[1] = g_lp;
    }
#undef DO_PHASE
}

extern "C" void kernel_launch(void* const* d_in, const int* in_sizes, int n_in,
                              void* d_out, int out_size) {
    (void)in_sizes; (void)n_in; (void)out_size;
    const float* g_emb_p    = (const float*)d_in[0];
    const float* W_ih_p     = (const float*)d_in[1];
    const float* W_hh_p     = (const float*)d_in[2];
    const float* b_ih_p     = (const float*)d_in[3];
    const float* b_hh_p     = (const float*)d_in[4];
    const float* ctx_W_p    = (const float*)d_in[5];
    const float* ctx_b_p    = (const float*)d_in[6];
    const float* left_W_p   = (const float*)d_in[7];
    const float* left_b_p   = (const float*)d_in[8];
    const int*   config_p   = (const int*)d_in[9];
    const int*   left_cfg_p = (const int*)d_in[10];
    float* out = (float*)d_out;

    static int smem_set = 0;
    if (!smem_set) {
        cudaFuncSetAttribute(controller_kernel,
                             cudaFuncAttributeMaxDynamicSharedMemorySize, SMEM_DYN);
        smem_set = 1;
    }

    controller_kernel<<<NB, NT, SMEM_DYN>>>(g_emb_p, W_ih_p, W_hh_p, b_ih_p, b_hh_p,
                                            ctx_W_p, ctx_b_p, left_W_p, left_b_p,
                                            config_p, left_cfg_p, out);
}

// round 7
// speedup vs baseline: 2.2332x; 1.6114x over previous
#include <cuda_runtime.h>
#include <math.h>

#define H    1024
#define NA   128
#define OP   16
#define G    32
#define UPB  7            // hidden units per block
#define NB   147          // 147*7 = 1029 >= 1024; all co-resident (<=148 SMs)
#define NT   480          // 15 warps: 14 compute (2 per unit) + 1 head warp
#define NW   15

typedef unsigned long long ull;

#define QSCALE   327670.0f         // |w| < 0.1 -> |q| <= 32767
#define QINV     (1.0f / 327670.0f)
#define DEC_BIAS (-8421376.0f)     // -(8388608 + 32768)

#define LAYER_STRIDE (UPB * 2 * 4 * H)          // u16 elements per layer per block
#define SMEM_DYN     (2 * LAYER_STRIDE * 2)     // bytes: 229376

// ---------------- persistent device state (no allocations allowed) ----------------
__device__ __align__(16) float g_h[2][2][2][H];   // [parity][substep][layer][j]
__device__ __align__(16) float g_c[2][2][2][H];
__device__ float g_ctx_logits[OP];
__device__ float g_left_logits[G];
__device__ float g_ent, g_lp;
__device__ volatile unsigned g_flags[160];        // all-to-all barrier flags (padded)

// ---------------- packed f32x2 helpers -------------------------------------------
__device__ __forceinline__ void fma2(ull& a, ull b, ull c) {
    asm("fma.rn.f32x2 %0, %1, %2, %0;" : "+l"(a) : "l"(b), "l"(c));
}
__device__ __forceinline__ ull pack2(float x, float y) {
    ull v; asm("mov.b64 %0, {%1, %2};" : "=l"(v) : "f"(x), "f"(y)); return v;
}
__device__ __forceinline__ float2 unpack2(ull v) {
    float2 f; asm("mov.b64 {%0, %1}, %2;" : "=f"(f.x), "=f"(f.y) : "l"(v)); return f;
}
// exact biased-u16 pair -> f32x2 of original int16 values (PRMT splice, no cvt)
__device__ __forceinline__ ull dec2(unsigned w, unsigned magic, ull bias2) {
    unsigned lo, hi;
    asm("prmt.b32 %0, %1, %2, 0x7410;" : "=r"(lo) : "r"(w), "r"(magic));
    asm("prmt.b32 %0, %1, %2, 0x7432;" : "=r"(hi) : "r"(w), "r"(magic));
    ull v;
    asm("mov.b64 %0, {%1, %2};" : "=l"(v) : "r"(lo), "r"(hi));
    asm("add.rn.f32x2 %0, %0, %1;" : "+l"(v) : "l"(bias2));
    return v;
}

__device__ __forceinline__ float warp_reduce(float v) {
#pragma unroll
    for (int o = 16; o; o >>= 1) v += __shfl_xor_sync(0xffffffffu, v, o);
    return v;
}
__device__ __forceinline__ float dot4(float4 a, float4 b) {
    return a.x * b.x + a.y * b.y + a.z * b.z + a.w * b.w;
}

// ---------------- all-to-all grid barrier (flag per block, replay-safe) -----------
__device__ __forceinline__ void grid_barrier(unsigned target, int lane) {
    __threadfence();
    __syncthreads();
    if (threadIdx.x == 0) g_flags[blockIdx.x] = target;
    if (threadIdx.x < 32) {
        for (;;) {
            bool ok = true;
#pragma unroll
            for (int k = 0; k < 5; ++k) {
                int idx = k * 32 + lane;
                unsigned f = g_flags[idx];
                ok &= (idx >= NB) | ((int)(f - target) >= 0);
            }
            if (__all_sync(0xffffffffu, ok)) break;
        }
        __threadfence();
    }
    __syncthreads();
}

// per-warp partial: 4 gate rows (u16, SMEM) . vec (fp32, global), 1024 cols.
__device__ __forceinline__ void lstm_partial(
    const unsigned short* wbase,            // SMEM: [4][1024] u16 rows
    const float* __restrict__ vec,          // global: 1024 floats
    int lane, float p[4])
{
    const unsigned magic = 0x4B000000u;
    const ull bias2 = pack2(DEC_BIAS, DEC_BIAS);
    ull acc[4] = {0, 0, 0, 0};

#pragma unroll
    for (int k = 0; k < 4; ++k) {
        const int c16 = k * 32 + lane;                  // 16B chunk id (0..127)
        const float4* vp = (const float4*)vec + c16 * 2;
        float4 va = vp[0], vb = vp[1];                  // 8 cols of vec
        ull v0 = pack2(va.x, va.y), v1 = pack2(va.z, va.w);
        ull v2 = pack2(vb.x, vb.y), v3 = pack2(vb.z, vb.w);
#pragma unroll
        for (int r = 0; r < 4; ++r) {
            uint4 w = ((const uint4*)(wbase + r * H))[c16];   // LDS.128
            fma2(acc[r], dec2(w.x, magic, bias2), v0);
            fma2(acc[r], dec2(w.y, magic, bias2), v1);
            fma2(acc[r], dec2(w.z, magic, bias2), v2);
            fma2(acc[r], dec2(w.w, magic, bias2), v3);
        }
    }
#pragma unroll
    for (int g = 0; g < 4; ++g) {
        float2 s = unpack2(acc[g]);
        p[g] = warp_reduce(s.x + s.y);
    }
}

// head row dot: fp32 weight row (global, streaming) . x (global)
__device__ __forceinline__ float head_dot(const float* __restrict__ w,
                                          const float* __restrict__ x, int lane) {
    const float4* wv = (const float4*)w;
    const float4* xv = (const float4*)x;
    float a = 0.f;
#pragma unroll
    for (int it = 0; it < 8; ++it) {
        int t = it * 32 + lane;
        a += dot4(__ldcs(wv + t), xv[t]);
    }
    return warp_reduce(a);
}

// warp-parallel log-softmax + entropy/log-prob accumulation (deterministic).
// Must be called by all 32 lanes of the acc head warp.
__device__ __forceinline__ void warp_softmax_acc(const float* __restrict__ logits,
                                                 int n, int chosen, int lane) {
    float v = (lane < n) ? logits[lane] : -1e30f;
    float m = v;
#pragma unroll
    for (int o = 16; o; o >>= 1) m = fmaxf(m, __shfl_xor_sync(0xffffffffu, m, o));
    float e = (lane < n) ? expf(v - m) : 0.f;
    float se = e;
#pragma unroll
    for (int o = 16; o; o >>= 1) se += __shfl_xor_sync(0xffffffffu, se, o);
    float lse = m + logf(se);
    float ls = v - lse;
    float t = (lane < n) ? expf(ls) * ls : 0.f;
#pragma unroll
    for (int o = 16; o; o >>= 1) t += __shfl_xor_sync(0xffffffffu, t, o);
    float lsc = __shfl_sync(0xffffffffu, ls, chosen);
    if (lane == 0) { g_ent += -t; g_lp += lsc; }
}

// ---------------- the single persistent kernel ------------------------------------
__global__ void __launch_bounds__(NT, 1)
controller_kernel(const float* __restrict__ g_emb,
                  const float* __restrict__ W_ih, const float* __restrict__ W_hh,
                  const float* __restrict__ b_ih, const float* __restrict__ b_hh,
                  const float* __restrict__ ctx_W, const float* __restrict__ ctx_b,
                  const float* __restrict__ left_W, const float* __restrict__ left_b,
                  const int* __restrict__ config, const int* __restrict__ left_config,
                  float* __restrict__ out)
{
    extern __shared__ unsigned short w_s[];           // [2][UPB][2][4][H] u16
    __shared__ float s_part[NW][4];
    __shared__ int   s_cfg[NA], s_lcfg[NA];
    __shared__ unsigned s_base;

    const int tid  = threadIdx.x;
    const int lane = tid & 31;
    const int wid  = tid >> 5;                         // 0..14
    const int bid  = blockIdx.x;
    const int u    = wid >> 1;                         // unit within block (compute warps)
    const int m    = wid & 1;                          // 0 = ih (x), 1 = hh (h)
    const int j    = bid * UPB + u;
    const bool active = (wid < 14) && (j < H);

    const bool leftw = (wid == 14) && ((bid & 3) == 0) && ((bid >> 2) < G);
    const int  leftr = bid >> 2;
    const bool ctxw  = (wid == 14) && ((bid & 7) == 0) && ((bid >> 3) < OP);
    const int  ctxr  = bid >> 3;
    const bool accW  = (bid == 1) && (wid == 14);      // acc = whole head warp of bid 1

    // ---------------- prologue: fill SMEM weights (quantize fp32 -> biased u16) ----
    if (tid == 0) s_base = g_flags[bid];
    if (accW && lane == 0) { g_ent = 0.f; g_lp = 0.f; }
    if (tid < NA) { s_cfg[tid] = config[tid]; s_lcfg[tid] = left_config[tid]; }

    for (int idx = tid; idx < 2 * UPB * 2 * 4 * (H / 4); idx += NT) {
        int col = (idx & 255) * 4;                 // 256 float4 per row
        int t   = idx >> 8;
        int r   = t & 3;  t >>= 2;
        int mm  = t & 1;  t >>= 1;
        int k   = t % UPB;
        int l   = t / UPB;
        int jj  = bid * UPB + k;
        if (jj < H) {
            const float* src = (mm ? W_hh : W_ih) +
                               (size_t)l * 4 * H * H + ((size_t)r * H + jj) * H + col;
            float4 v = __ldcs((const float4*)src);
            ushort4 q;
            q.x = (unsigned short)(__float2int_rn(v.x * QSCALE) + 32768);
            q.y = (unsigned short)(__float2int_rn(v.y * QSCALE) + 32768);
            q.z = (unsigned short)(__float2int_rn(v.z * QSCALE) + 32768);
            q.w = (unsigned short)(__float2int_rn(v.w * QSCALE) + 32768);
            *(ushort4*)(w_s + ((((size_t)l * UPB + k) * 2 + mm) * 4 + r) * H + col) = q;
        }
    }

    // per-finalize-thread bias registers: bsr[l*4+g]
    const int jt = bid * UPB + tid;                    // unit for finalize thread tid<UPB
    const bool jt_ok = (tid < UPB) && (jt < H);
    float bsr[8];
    if (jt_ok) {
#pragma unroll
        for (int l = 0; l < 2; ++l)
#pragma unroll
            for (int g = 0; g < 4; ++g)
                bsr[l * 4 + g] = b_ih[l * 4 * H + g * H + jt] + b_hh[l * 4 * H + g * H + jt];
    }
    __syncthreads();
    unsigned bar = s_base;

    const unsigned short* wb0 = w_s + ((size_t)u * 2 + m) * 4 * H;       // layer 0
    const unsigned short* wb1 = wb0 + LAYER_STRIDE;                      // layer 1

#define DO_PHASE(WB, XV, HV, ZERO_H, CPRE, ZERO_C, HOUT, COUT, LIDX)            \
    do {                                                                        \
        float cpre_r = 0.f;                                                     \
        if (jt_ok && !(ZERO_C)) cpre_r = (CPRE)[jt];                            \
        if (active) {                                                           \
            float prt[4];                                                       \
            if (m == 0)            lstm_partial((WB), (XV), lane, prt);         \
            else if (ZERO_H)       { prt[0]=prt[1]=prt[2]=prt[3]=0.f; }         \
            else                   lstm_partial((WB), (HV), lane, prt);         \
            if (lane == 0) { s_part[wid][0]=prt[0]; s_part[wid][1]=prt[1];      \
                             s_part[wid][2]=prt[2]; s_part[wid][3]=prt[3]; }    \
        }                                                                       \
        HEADCODE;                                                               \
        __syncthreads();                                                        \
        if (jt_ok) {                                                            \
            float zi = (s_part[2*tid][0]+s_part[2*tid+1][0])*QINV + bsr[(LIDX)*4+0]; \
            float zf = (s_part[2*tid][1]+s_part[2*tid+1][1])*QINV + bsr[(LIDX)*4+1]; \
            float zg = (s_part[2*tid][2]+s_part[2*tid+1][2])*QINV + bsr[(LIDX)*4+2]; \
            float zo = (s_part[2*tid][3]+s_part[2*tid+1][3])*QINV + bsr[(LIDX)*4+3]; \
            float ii = 1.f/(1.f+expf(-zi));                                     \
            float ff = 1.f/(1.f+expf(-zf));                                     \
            float gg = tanhf(zg);                                               \
            float oo = 1.f/(1.f+expf(-zo));                                     \
            float cn = ff*cpre_r + ii*gg;                                       \
            (COUT)[jt] = cn;                                                    \
            (HOUT)[jt] = oo*tanhf(cn);                                          \
        }                                                                       \
        grid_barrier(++bar, lane);                                              \
    } while (0)

    for (int a = 0; a < NA; ++a) {
        const int  q     = a & 1;
        const int  p     = q ^ 1;
        const bool first = (a == 0);
        const int  prevgap = first ? 0 : (s_cfg[a - 1] == 1);
        const int  sel   = prevgap;                    // state branch taken last step
        const bool gap   = (s_cfg[a] == 1);            // run gap phases this step?

        // ---- PHASE A: substep 0, layer 0 ------------------------------------------
        // head warp: if prev step had a gap -> left dots(a-1); else -> ctx dots(a-1)
#define HEADCODE                                                                \
        if (!first) {                                                           \
            if (prevgap) {                                                      \
                if (leftw) {                                                    \
                    float d = head_dot(left_W + ((size_t)(a-1) * G + leftr) * H,\
                                       g_h[p][1][1], lane);                     \
                    if (lane == 0) g_left_logits[leftr] = d + left_b[(a-1)*G + leftr]; \
                }                                                               \
            } else {                                                            \
                if (ctxw) {                                                     \
                    float d = head_dot(ctx_W + ((size_t)(a-1) * OP + ctxr) * H, \
                                       g_h[p][0][1], lane);                     \
                    if (lane == 0) g_ctx_logits[ctxr] = d + ctx_b[(a-1)*OP + ctxr]; \
                }                                                               \
            }                                                                   \
        }
        DO_PHASE(wb0, (first ? g_emb : g_h[p][sel][1]), g_h[p][sel][0], first,
                 g_c[p][sel][0], first, g_h[q][0][0], g_c[q][0][0], 0);
#undef HEADCODE

        // ---- PHASE B: substep 0, layer 1 ------------------------------------------
        // acc warp: finish prev step's pending softmax (left if gap, else ctx)
#define HEADCODE                                                                \
        if (!first && accW) {                                                   \
            if (prevgap) warp_softmax_acc(g_left_logits, G, s_lcfg[a-1], lane); \
            else         warp_softmax_acc(g_ctx_logits, OP, s_cfg[a-1], lane);  \
        }
        DO_PHASE(wb1, g_h[q][0][0], g_h[p][sel][1], first,
                 g_c[p][sel][1], first, g_h[q][0][1], g_c[q][0][1], 1);
#undef HEADCODE

        if (gap) {
            // ---- PHASE C: substep 1 (gap), layer 0; head warp: ctx dots(a) --------
#define HEADCODE                                                                \
            if (ctxw) {                                                         \
                float d = head_dot(ctx_W + ((size_t)a * OP + ctxr) * H,         \
                                   g_h[q][0][1], lane);                         \
                if (lane == 0) g_ctx_logits[ctxr] = d + ctx_b[a * OP + ctxr];   \
            }
            DO_PHASE(wb0, g_h[q][0][1], g_h[q][0][0], false,
                     g_c[q][0][0], false, g_h[q][1][0], g_c[q][1][0], 0);
#undef HEADCODE

            // ---- PHASE D: substep 1 (gap), layer 1; acc warp: ctx softmax(a) ------
#define HEADCODE                                                                \
            if (accW) warp_softmax_acc(g_ctx_logits, OP, s_cfg[a], 1 ? lane : lane)
            DO_PHASE(wb1, g_h[q][1][0], g_h[q][0][1], false,
                     g_c[q][0][1], false, g_h[q][1][1], g_c[q][1][1], 1);
#undef HEADCODE
        }
        // if !gap: phases C/D contribute exactly 0 to ent/lp and leave state
        // untouched (mask mf == 0 in the reference) -> skipped entirely.
        // ctx(a) dots/softmax are deferred to phases A/B of step a+1.
    }

    // ---- epilogue: pending head work for the final step (parity 1) ----------------
    {
        const int lastgap = (s_cfg[NA - 1] == 1);
        if (lastgap) {
            if (leftw) {
                float d = head_dot(left_W + ((size_t)(NA - 1) * G + leftr) * H,
                                   g_h[1][1][1], lane);
                if (lane == 0) g_left_logits[leftr] = d + left_b[(NA - 1) * G + leftr];
            }
        } else {
            if (ctxw) {
                float d = head_dot(ctx_W + ((size_t)(NA - 1) * OP + ctxr) * H,
                                   g_h[1][0][1], lane);
                if (lane == 0) g_ctx_logits[ctxr] = d + ctx_b[(NA - 1) * OP + ctxr];
            }
        }
        grid_barrier(++bar, lane);
        if (accW) {
            if (lastgap) warp_softmax_acc(g_left_logits, G, s_lcfg[NA - 1], lane);
            else         warp_softmax_acc(g_ctx_logits, OP, s_cfg[NA - 1], lane);
            if (lane == 0) { out[0] = g_ent; out[1] = g_lp; }
        }
    }
#undef DO_PHASE
}

extern "C" void kernel_launch(void* const* d_in, const int* in_sizes, int n_in,
                              void* d_out, int out_size) {
    (void)in_sizes; (void)n_in; (void)out_size;
    const float* g_emb_p    = (const float*)d_in[0];
    const float* W_ih_p     = (const float*)d_in[1];
    const float* W_hh_p     = (const float*)d_in[2];
    const float* b_ih_p     = (const float*)d_in[3];
    const float* b_hh_p     = (const float*)d_in[4];
    const float* ctx_W_p    = (const float*)d_in[5];
    const float* ctx_b_p    = (const float*)d_in[6];
    const float* left_W_p   = (const float*)d_in[7];
    const float* left_b_p   = (const float*)d_in[8];
    const int*   config_p   = (const int*)d_in[9];
    const int*   left_cfg_p = (const int*)d_in[10];
    float* out = (float*)d_out;

    static int smem_set = 0;
    if (!smem_set) {
        cudaFuncSetAttribute(controller_kernel,
                             cudaFuncAttributeMaxDynamicSharedMemorySize, SMEM_DYN);
        smem_set = 1;
    }

    controller_kernel<<<NB, NT, SMEM_DYN>>>(g_emb_p, W_ih_p, W_hh_p, b_ih_p, b_hh_p,
                                            ctx_W_p, ctx_b_p, left_W_p, left_b_p,
                                            config_p, left_cfg_p, out);
}

// round 8
// speedup vs baseline: 3.0483x; 1.3650x over previous
#include <cuda_runtime.h>
#include <math.h>

#define H    1024
#define NA   128
#define OP   16
#define G    32
#define UPB  7            // hidden units per block
#define NB   147          // 147*7 = 1029 >= 1024; all co-resident (<=148 SMs)
#define NT   480          // 15 warps: 14 compute (2 per unit) + 1 head warp
#define NW   15

typedef unsigned long long ull;

#define QSCALE   327670.0f         // |w| < 0.1 -> |q| <= 32767
#define QINV     (1.0f / 327670.0f)
#define DEC_BIAS (-8421376.0f)     // -(8388608 + 32768)

#define LAYER_STRIDE (UPB * 2 * 4 * H)          // u16 elements per layer per block
#define SMEM_DYN     (2 * LAYER_STRIDE * 2)     // bytes: 229376

// ---------------- persistent device state (no allocations allowed) ----------------
__device__ __align__(16) float g_h[2][2][2][H];   // [parity][substep][layer][j]
__device__ __align__(16) float g_c[2][2][2][H];
__device__ float g_ctx_logits[OP];
__device__ float g_left_logits[G];
__device__ unsigned g_flags[160];                 // all-to-all barrier flags (padded)

// ---------------- packed f32x2 helpers -------------------------------------------
__device__ __forceinline__ void fma2(ull& a, ull b, ull c) {
    asm("fma.rn.f32x2 %0, %1, %2, %0;" : "+l"(a) : "l"(b), "l"(c));
}
__device__ __forceinline__ ull pack2(float x, float y) {
    ull v; asm("mov.b64 %0, {%1, %2};" : "=l"(v) : "f"(x), "f"(y)); return v;
}
__device__ __forceinline__ float2 unpack2(ull v) {
    float2 f; asm("mov.b64 {%0, %1}, %2;" : "=f"(f.x), "=f"(f.y) : "l"(v)); return f;
}
// exact biased-u16 pair -> f32x2 of original int16 values (PRMT splice, no cvt)
__device__ __forceinline__ ull dec2(unsigned w, unsigned magic, ull bias2) {
    unsigned lo, hi;
    asm("prmt.b32 %0, %1, %2, 0x7410;" : "=r"(lo) : "r"(w), "r"(magic));
    asm("prmt.b32 %0, %1, %2, 0x7432;" : "=r"(hi) : "r"(w), "r"(magic));
    ull v;
    asm("mov.b64 %0, {%1, %2};" : "=l"(v) : "r"(lo), "r"(hi));
    asm("add.rn.f32x2 %0, %0, %1;" : "+l"(v) : "l"(bias2));
    return v;
}

__device__ __forceinline__ float warp_reduce(float v) {
#pragma unroll
    for (int o = 16; o; o >>= 1) v += __shfl_xor_sync(0xffffffffu, v, o);
    return v;
}
__device__ __forceinline__ float dot4(float4 a, float4 b) {
    return a.x * b.x + a.y * b.y + a.z * b.z + a.w * b.w;
}

// ---------------- fence-free grid barrier (release/acquire through L2) ------------
// All shared data moves via .cg (L2-coherent, never in L1) => no L1 flush needed.
__device__ __forceinline__ void grid_barrier(unsigned target, int lane) {
    __syncthreads();
    if (threadIdx.x == 0) {
        asm volatile("st.release.gpu.global.u32 [%0], %1;"
                     :: "l"(&g_flags[blockIdx.x]), "r"(target) : "memory");
    }
    if (threadIdx.x < 32) {
        for (;;) {
            bool ok = true;
#pragma unroll
            for (int k = 0; k < 5; ++k) {
                int idx = k * 32 + lane;
                unsigned f;
                asm volatile("ld.acquire.gpu.global.u32 %0, [%1];"
                             : "=r"(f) : "l"(&g_flags[idx]) : "memory");
                ok &= (idx >= NB) | ((int)(f - target) >= 0);
            }
            if (__all_sync(0xffffffffu, ok)) break;
        }
    }
    __syncthreads();
}

// per-warp partial: 4 gate rows (u16, SMEM) . vec (fp32, global via L2), 1024 cols.
__device__ __forceinline__ void lstm_partial(
    const unsigned short* wbase,            // SMEM: [4][1024] u16 rows
    const float* __restrict__ vec,          // global: 1024 floats (L2-coherent)
    int lane, float p[4])
{
    const unsigned magic = 0x4B000000u;
    const ull bias2 = pack2(DEC_BIAS, DEC_BIAS);
    ull acc[4] = {0, 0, 0, 0};

#pragma unroll
    for (int k = 0; k < 4; ++k) {
        const int c16 = k * 32 + lane;                  // 16B chunk id (0..127)
        const float4* vp = (const float4*)vec + c16 * 2;
        float4 va = __ldcg(vp);
        float4 vb = __ldcg(vp + 1);
        ull v0 = pack2(va.x, va.y), v1 = pack2(va.z, va.w);
        ull v2 = pack2(vb.x, vb.y), v3 = pack2(vb.z, vb.w);
#pragma unroll
        for (int r = 0; r < 4; ++r) {
            uint4 w = ((const uint4*)(wbase + r * H))[c16];   // LDS.128
            fma2(acc[r], dec2(w.x, magic, bias2), v0);
            fma2(acc[r], dec2(w.y, magic, bias2), v1);
            fma2(acc[r], dec2(w.z, magic, bias2), v2);
            fma2(acc[r], dec2(w.w, magic, bias2), v3);
        }
    }
#pragma unroll
    for (int g = 0; g < 4; ++g) {
        float2 s = unpack2(acc[g]);
        p[g] = warp_reduce(s.x + s.y);
    }
}

// head row dot: fp32 weight row (global, streaming) . x (global via L2)
__device__ __forceinline__ float head_dot(const float* __restrict__ w,
                                          const float* __restrict__ x, int lane) {
    const float4* wv = (const float4*)w;
    const float4* xv = (const float4*)x;
    float a = 0.f;
#pragma unroll
    for (int it = 0; it < 8; ++it) {
        int t = it * 32 + lane;
        a += dot4(__ldcs(wv + t), __ldcg(xv + t));
    }
    return warp_reduce(a);
}

// warp-parallel log-softmax; accumulates into acc-warp registers (deterministic).
__device__ __forceinline__ void warp_softmax_acc(const float* __restrict__ logits,
                                                 int n, int chosen, int lane,
                                                 float& ent, float& lp) {
    float v = (lane < n) ? __ldcg(logits + lane) : -1e30f;
    float m = v;
#pragma unroll
    for (int o = 16; o; o >>= 1) m = fmaxf(m, __shfl_xor_sync(0xffffffffu, m, o));
    float e = (lane < n) ? expf(v - m) : 0.f;
    float se = e;
#pragma unroll
    for (int o = 16; o; o >>= 1) se += __shfl_xor_sync(0xffffffffu, se, o);
    float lse = m + logf(se);
    float ls = v - lse;
    float t = (lane < n) ? expf(ls) * ls : 0.f;
#pragma unroll
    for (int o = 16; o; o >>= 1) t += __shfl_xor_sync(0xffffffffu, t, o);
    float lsc = __shfl_sync(0xffffffffu, ls, chosen);
    ent += -t;
    lp  += lsc;
}

// ---------------- the single persistent kernel ------------------------------------
__global__ void __launch_bounds__(NT, 1)
controller_kernel(const float* __restrict__ g_emb,
                  const float* __restrict__ W_ih, const float* __restrict__ W_hh,
                  const float* __restrict__ b_ih, const float* __restrict__ b_hh,
                  const float* __restrict__ ctx_W, const float* __restrict__ ctx_b,
                  const float* __restrict__ left_W, const float* __restrict__ left_b,
                  const int* __restrict__ config, const int* __restrict__ left_config,
                  float* __restrict__ out)
{
    extern __shared__ unsigned short w_s[];           // [2][UPB][2][4][H] u16
    __shared__ float s_part[NW][4];
    __shared__ int   s_cfg[NA], s_lcfg[NA];
    __shared__ unsigned s_base;

    const int tid  = threadIdx.x;
    const int lane = tid & 31;
    const int wid  = tid >> 5;                         // 0..14
    const int bid  = blockIdx.x;
    const int u    = wid >> 1;                         // unit within block (compute warps)
    const int m    = wid & 1;                          // 0 = ih (x), 1 = hh (h)
    const int j    = bid * UPB + u;
    const bool active = (wid < 14) && (j < H);

    const bool leftw = (wid == 14) && ((bid & 3) == 0) && ((bid >> 2) < G);
    const int  leftr = bid >> 2;
    const bool ctxw  = (wid == 14) && ((bid & 7) == 0) && ((bid >> 3) < OP);
    const int  ctxr  = bid >> 3;
    const bool accW  = (bid == 1) && (wid == 14);      // acc = whole head warp of bid 1

    float ent = 0.f, lp = 0.f;                         // acc-warp registers

    // ---------------- prologue: fill SMEM weights (quantize fp32 -> biased u16) ----
    if (tid == 0) s_base = g_flags[bid];               // only this block writes it
    if (tid < NA) { s_cfg[tid] = config[tid]; s_lcfg[tid] = left_config[tid]; }

    for (int idx = tid; idx < 2 * UPB * 2 * 4 * (H / 4); idx += NT) {
        int col = (idx & 255) * 4;                 // 256 float4 per row
        int t   = idx >> 8;
        int r   = t & 3;  t >>= 2;
        int mm  = t & 1;  t >>= 1;
        int k   = t % UPB;
        int l   = t / UPB;
        int jj  = bid * UPB + k;
        if (jj < H) {
            const float* src = (mm ? W_hh : W_ih) +
                               (size_t)l * 4 * H * H + ((size_t)r * H + jj) * H + col;
            float4 v = __ldcs((const float4*)src);
            ushort4 q;
            q.x = (unsigned short)(__float2int_rn(v.x * QSCALE) + 32768);
            q.y = (unsigned short)(__float2int_rn(v.y * QSCALE) + 32768);
            q.z = (unsigned short)(__float2int_rn(v.z * QSCALE) + 32768);
            q.w = (unsigned short)(__float2int_rn(v.w * QSCALE) + 32768);
            *(ushort4*)(w_s + ((((size_t)l * UPB + k) * 2 + mm) * 4 + r) * H + col) = q;
        }
    }

    // per-finalize-thread bias registers: bsr[l*4+g]
    const int jt = bid * UPB + tid;                    // unit for finalize thread tid<UPB
    const bool jt_ok = (tid < UPB) && (jt < H);
    float bsr[8];
    if (jt_ok) {
#pragma unroll
        for (int l = 0; l < 2; ++l)
#pragma unroll
            for (int g = 0; g < 4; ++g)
                bsr[l * 4 + g] = b_ih[l * 4 * H + g * H + jt] + b_hh[l * 4 * H + g * H + jt];
    }
    __syncthreads();
    unsigned bar = s_base;

    const unsigned short* wb0 = w_s + ((size_t)u * 2 + m) * 4 * H;       // layer 0
    const unsigned short* wb1 = wb0 + LAYER_STRIDE;                      // layer 1

#define DO_PHASE(WB, XV, HV, ZERO_H, CPRE, ZERO_C, HOUT, COUT, LIDX)            \
    do {                                                                        \
        float cpre_r = 0.f;                                                     \
        if (jt_ok && !(ZERO_C)) cpre_r = __ldcg(&(CPRE)[jt]);                   \
        if (active) {                                                           \
            float prt[4];                                                       \
            if (m == 0)            lstm_partial((WB), (XV), lane, prt);         \
            else if (ZERO_H)       { prt[0]=prt[1]=prt[2]=prt[3]=0.f; }         \
            else                   lstm_partial((WB), (HV), lane, prt);         \
            if (lane == 0) { s_part[wid][0]=prt[0]; s_part[wid][1]=prt[1];      \
                             s_part[wid][2]=prt[2]; s_part[wid][3]=prt[3]; }    \
        }                                                                       \
        HEADCODE;                                                               \
        __syncthreads();                                                        \
        if (jt_ok) {                                                            \
            float zi = (s_part[2*tid][0]+s_part[2*tid+1][0])*QINV + bsr[(LIDX)*4+0]; \
            float zf = (s_part[2*tid][1]+s_part[2*tid+1][1])*QINV + bsr[(LIDX)*4+1]; \
            float zg = (s_part[2*tid][2]+s_part[2*tid+1][2])*QINV + bsr[(LIDX)*4+2]; \
            float zo = (s_part[2*tid][3]+s_part[2*tid+1][3])*QINV + bsr[(LIDX)*4+3]; \
            float ii = 1.f/(1.f+expf(-zi));                                     \
            float ff = 1.f/(1.f+expf(-zf));                                     \
            float gg = tanhf(zg);                                               \
            float oo = 1.f/(1.f+expf(-zo));                                     \
            float cn = ff*cpre_r + ii*gg;                                       \
            __stcg(&(COUT)[jt], cn);                                            \
            __stcg(&(HOUT)[jt], oo*tanhf(cn));                                  \
        }                                                                       \
        grid_barrier(++bar, lane);                                              \
    } while (0)

    for (int a = 0; a < NA; ++a) {
        const int  q     = a & 1;
        const int  p     = q ^ 1;
        const bool first = (a == 0);
        const int  prevgap = first ? 0 : (s_cfg[a - 1] == 1);
        const int  sel   = prevgap;                    // state branch taken last step
        const bool gap   = (s_cfg[a] == 1);            // run gap phases this step?

        // ---- PHASE A: substep 0, layer 0 ------------------------------------------
        // head warp: if prev step had a gap -> left dots(a-1); else -> ctx dots(a-1)
#define HEADCODE                                                                \
        if (!first) {                                                           \
            if (prevgap) {                                                      \
                if (leftw) {                                                    \
                    float d = head_dot(left_W + ((size_t)(a-1) * G + leftr) * H,\
                                       g_h[p][1][1], lane);                     \
                    if (lane == 0) __stcg(&g_left_logits[leftr],                \
                                          d + left_b[(a-1)*G + leftr]);         \
                }                                                               \
            } else {                                                            \
                if (ctxw) {                                                     \
                    float d = head_dot(ctx_W + ((size_t)(a-1) * OP + ctxr) * H, \
                                       g_h[p][0][1], lane);                     \
                    if (lane == 0) __stcg(&g_ctx_logits[ctxr],                  \
                                          d + ctx_b[(a-1)*OP + ctxr]);          \
                }                                                               \
            }                                                                   \
        }
        DO_PHASE(wb0, (first ? g_emb : g_h[p][sel][1]), g_h[p][sel][0], first,
                 g_c[p][sel][0], first, g_h[q][0][0], g_c[q][0][0], 0);
#undef HEADCODE

        // ---- PHASE B: substep 0, layer 1 ------------------------------------------
        // acc warp: finish prev step's pending softmax (left if gap, else ctx)
#define HEADCODE                                                                \
        if (!first && accW) {                                                   \
            if (prevgap) warp_softmax_acc(g_left_logits, G, s_lcfg[a-1], lane,  \
                                          ent, lp);                             \
            else         warp_softmax_acc(g_ctx_logits, OP, s_cfg[a-1], lane,   \
                                          ent, lp);                             \
        }
        DO_PHASE(wb1, g_h[q][0][0], g_h[p][sel][1], first,
                 g_c[p][sel][1], first, g_h[q][0][1], g_c[q][0][1], 1);
#undef HEADCODE

        if (gap) {
            // ---- PHASE C: substep 1 (gap), layer 0; head warp: ctx dots(a) --------
#define HEADCODE                                                                \
            if (ctxw) {                                                         \
                float d = head_dot(ctx_W + ((size_t)a * OP + ctxr) * H,         \
                                   g_h[q][0][1], lane);                         \
                if (lane == 0) __stcg(&g_ctx_logits[ctxr],                      \
                                      d + ctx_b[a * OP + ctxr]);                \
            }
            DO_PHASE(wb0, g_h[q][0][1], g_h[q][0][0], false,
                     g_c[q][0][0], false, g_h[q][1][0], g_c[q][1][0], 0);
#undef HEADCODE

            // ---- PHASE D: substep 1 (gap), layer 1; acc warp: ctx softmax(a) ------
#define HEADCODE                                                                \
            if (accW) warp_softmax_acc(g_ctx_logits, OP, s_cfg[a], lane, ent, lp)
            DO_PHASE(wb1, g_h[q][1][0], g_h[q][0][1], false,
                     g_c[q][0][1], false, g_h[q][1][1], g_c[q][1][1], 1);
#undef HEADCODE
        }
        // if !gap: phases C/D contribute exactly 0 to ent/lp and leave state
        // untouched (mask mf == 0 in the reference) -> skipped entirely.
    }

    // ---- epilogue: pending head work for the final step (parity 1) ----------------
    {
        const int lastgap = (s_cfg[NA - 1] == 1);
        if (lastgap) {
            if (leftw) {
                float d = head_dot(left_W + ((size_t)(NA - 1) * G + leftr) * H,
                                   g_h[1][1][1], lane);
                if (lane == 0) __stcg(&g_left_logits[leftr],
                                      d + left_b[(NA - 1) * G + leftr]);
            }
        } else {
            if (ctxw) {
                float d = head_dot(ctx_W + ((size_t)(NA - 1) * OP + ctxr) * H,
                                   g_h[1][0][1], lane);
                if (lane == 0) __stcg(&g_ctx_logits[ctxr],
                                      d + ctx_b[(NA - 1) * OP + ctxr]);
            }
        }
        grid_barrier(++bar, lane);
        if (accW) {
            if (lastgap) warp_softmax_acc(g_left_logits, G, s_lcfg[NA - 1], lane, ent, lp);
            else         warp_softmax_acc(g_ctx_logits, OP, s_cfg[NA - 1], lane, ent, lp);
            if (lane == 0) { out[0] = ent; out[1] = lp; }
        }
    }
#undef DO_PHASE
}

extern "C" void kernel_launch(void* const* d_in, const int* in_sizes, int n_in,
                              void* d_out, int out_size) {
    (void)in_sizes; (void)n_in; (void)out_size;
    const float* g_emb_p    = (const float*)d_in[0];
    const float* W_ih_p     = (const float*)d_in[1];
    const float* W_hh_p     = (const float*)d_in[2];
    const float* b_ih_p     = (const float*)d_in[3];
    const float* b_hh_p     = (const float*)d_in[4];
    const float* ctx_W_p    = (const float*)d_in[5];
    const float* ctx_b_p    = (const float*)d_in[6];
    const float* left_W_p   = (const float*)d_in[7];
    const float* left_b_p   = (const float*)d_in[8];
    const int*   config_p   = (const int*)d_in[9];
    const int*   left_cfg_p = (const int*)d_in[10];
    float* out = (float*)d_out;

    static int smem_set = 0;
    if (!smem_set) {
        cudaFuncSetAttribute(controller_kernel,
                             cudaFuncAttributeMaxDynamicSharedMemorySize, SMEM_DYN);
        smem_set = 1;
    }

    controller_kernel<<<NB, NT, SMEM_DYN>>>(g_emb_p, W_ih_p, W_hh_p, b_ih_p, b_hh_p,
                                            ctx_W_p, ctx_b_p, left_W_p, left_b_p,
                                            config_p, left_cfg_p, out);
}

// round 9
// speedup vs baseline: 4.6301x; 1.5189x over previous
#include <cuda_runtime.h>
#include <math.h>

#define H    1024
#define NA   128
#define OP   16
#define G    32
#define UPB  7            // hidden units per block
#define NB   147          // 147*7 = 1029 >= 1024; all co-resident (<=148 SMs)
#define NT   480          // 15 warps: 14 compute (2 per unit) + 1 head warp
#define NW   15

typedef unsigned long long ull;

#define QSCALE   327670.0f         // |w| < 0.1 -> |q| <= 32767
#define QINV     (1.0f / 327670.0f)
#define DEC_BIAS (-8421376.0f)     // -(8388608 + 32768)

#define LAYER_STRIDE (UPB * 2 * 4 * H)          // u16 elements per layer per block
#define SMEM_DYN     (2 * LAYER_STRIDE * 2)     // bytes: 229376

// ---------------- persistent device state (no allocations allowed) ----------------
__device__ __align__(16) float g_h[2][2][2][H];   // [parity][substep][layer][j]
__device__ __align__(16) float g_c[2][2][2][H];
__device__ float g_ctx_logits[OP];
__device__ float g_left_logits[G];
__device__ unsigned g_count;                      // barrier counter; 0 at launch start
__device__ unsigned g_flags[160];                 // per-block epochs (final barrier)

// ---------------- packed f32x2 helpers -------------------------------------------
__device__ __forceinline__ void fma2(ull& a, ull b, ull c) {
    asm("fma.rn.f32x2 %0, %1, %2, %0;" : "+l"(a) : "l"(b), "l"(c));
}
__device__ __forceinline__ ull pack2(float x, float y) {
    ull v; asm("mov.b64 %0, {%1, %2};" : "=l"(v) : "f"(x), "f"(y)); return v;
}
__device__ __forceinline__ float2 unpack2(ull v) {
    float2 f; asm("mov.b64 {%0, %1}, %2;" : "=f"(f.x), "=f"(f.y) : "l"(v)); return f;
}
// exact biased-u16 pair -> f32x2 of original int16 values (PRMT splice, no cvt)
__device__ __forceinline__ ull dec2(unsigned w, unsigned magic, ull bias2) {
    unsigned lo, hi;
    asm("prmt.b32 %0, %1, %2, 0x7410;" : "=r"(lo) : "r"(w), "r"(magic));
    asm("prmt.b32 %0, %1, %2, 0x7432;" : "=r"(hi) : "r"(w), "r"(magic));
    ull v;
    asm("mov.b64 %0, {%1, %2};" : "=l"(v) : "r"(lo), "r"(hi));
    asm("add.rn.f32x2 %0, %0, %1;" : "+l"(v) : "l"(bias2));
    return v;
}

__device__ __forceinline__ float warp_reduce(float v) {
#pragma unroll
    for (int o = 16; o; o >>= 1) v += __shfl_xor_sync(0xffffffffu, v, o);
    return v;
}
__device__ __forceinline__ float dot4(float4 a, float4 b) {
    return a.x * b.x + a.y * b.y + a.z * b.z + a.w * b.w;
}

// ---------------- single-counter grid barrier (1 RED + 1-word poll) ---------------
// Counter is 0 at launch start (reset at end of previous launch). Barrier k waits
// for count >= k*NB. Only thread 0 polls; everyone else waits at bar.sync.
__device__ __forceinline__ void grid_barrier(unsigned k) {
    const unsigned target = k * (unsigned)NB;
    __syncthreads();
    if (threadIdx.x == 0) {
        asm volatile("red.release.gpu.global.add.u32 [%0], 1;"
                     :: "l"(&g_count) : "memory");
        unsigned v;
        do {
            asm volatile("ld.acquire.gpu.global.u32 %0, [%1];"
                         : "=r"(v) : "l"(&g_count) : "memory");
        } while ((int)(v - target) < 0);
    }
    __syncthreads();
}

// all-to-all flags barrier: used ONCE at kernel end to make the counter reset safe.
__device__ __forceinline__ void flags_barrier(unsigned target, int lane) {
    __syncthreads();
    if (threadIdx.x == 0)
        asm volatile("st.release.gpu.global.u32 [%0], %1;"
                     :: "l"(&g_flags[blockIdx.x]), "r"(target) : "memory");
    if (threadIdx.x < 32) {
        for (;;) {
            bool ok = true;
#pragma unroll
            for (int k = 0; k < 5; ++k) {
                int idx = k * 32 + lane;
                unsigned f;
                asm volatile("ld.acquire.gpu.global.u32 %0, [%1];"
                             : "=r"(f) : "l"(&g_flags[idx]) : "memory");
                ok &= (idx >= NB) | ((int)(f - target) >= 0);
            }
            if (__all_sync(0xffffffffu, ok)) break;
        }
    }
    __syncthreads();
}

// per-warp partial: 4 gate rows (u16, SMEM) . vec (fp32, global via L2), 1024 cols.
__device__ __forceinline__ void lstm_partial(
    const unsigned short* wbase,            // SMEM: [4][1024] u16 rows
    const float* __restrict__ vec,          // global: 1024 floats (L2-coherent)
    int lane, float p[4])
{
    const unsigned magic = 0x4B000000u;
    const ull bias2 = pack2(DEC_BIAS, DEC_BIAS);
    ull acc[4] = {0, 0, 0, 0};

#pragma unroll
    for (int k = 0; k < 4; ++k) {
        const int c16 = k * 32 + lane;                  // 16B chunk id (0..127)
        const float4* vp = (const float4*)vec + c16 * 2;
        float4 va = __ldcg(vp);
        float4 vb = __ldcg(vp + 1);
        ull v0 = pack2(va.x, va.y), v1 = pack2(va.z, va.w);
        ull v2 = pack2(vb.x, vb.y), v3 = pack2(vb.z, vb.w);
#pragma unroll
        for (int r = 0; r < 4; ++r) {
            uint4 w = ((const uint4*)(wbase + r * H))[c16];   // LDS.128
            fma2(acc[r], dec2(w.x, magic, bias2), v0);
            fma2(acc[r], dec2(w.y, magic, bias2), v1);
            fma2(acc[r], dec2(w.z, magic, bias2), v2);
            fma2(acc[r], dec2(w.w, magic, bias2), v3);
        }
    }
#pragma unroll
    for (int g = 0; g < 4; ++g) {
        float2 s = unpack2(acc[g]);
        p[g] = warp_reduce(s.x + s.y);
    }
}

// head row dot: fp32 weight row (global, streaming) . x (global via L2)
__device__ __forceinline__ float head_dot(const float* __restrict__ w,
                                          const float* __restrict__ x, int lane) {
    const float4* wv = (const float4*)w;
    const float4* xv = (const float4*)x;
    float a = 0.f;
#pragma unroll
    for (int it = 0; it < 8; ++it) {
        int t = it * 32 + lane;
        a += dot4(__ldcs(wv + t), __ldcg(xv + t));
    }
    return warp_reduce(a);
}

// warp-parallel log-softmax; accumulates into acc-warp registers (deterministic).
__device__ __forceinline__ void warp_softmax_acc(const float* __restrict__ logits,
                                                 int n, int chosen, int lane,
                                                 float& ent, float& lp) {
    float v = (lane < n) ? __ldcg(logits + lane) : -1e30f;
    float m = v;
#pragma unroll
    for (int o = 16; o; o >>= 1) m = fmaxf(m, __shfl_xor_sync(0xffffffffu, m, o));
    float e = (lane < n) ? expf(v - m) : 0.f;
    float se = e;
#pragma unroll
    for (int o = 16; o; o >>= 1) se += __shfl_xor_sync(0xffffffffu, se, o);
    float lse = m + logf(se);
    float ls = v - lse;
    float t = (lane < n) ? expf(ls) * ls : 0.f;
#pragma unroll
    for (int o = 16; o; o >>= 1) t += __shfl_xor_sync(0xffffffffu, t, o);
    float lsc = __shfl_sync(0xffffffffu, ls, chosen);
    ent += -t;
    lp  += lsc;
}

// ---------------- the single persistent kernel ------------------------------------
__global__ void __launch_bounds__(NT, 1)
controller_kernel(const float* __restrict__ g_emb,
                  const float* __restrict__ W_ih, const float* __restrict__ W_hh,
                  const float* __restrict__ b_ih, const float* __restrict__ b_hh,
                  const float* __restrict__ ctx_W, const float* __restrict__ ctx_b,
                  const float* __restrict__ left_W, const float* __restrict__ left_b,
                  const int* __restrict__ config, const int* __restrict__ left_config,
                  float* __restrict__ out)
{
    extern __shared__ unsigned short w_s[];           // [2][UPB][2][4][H] u16
    __shared__ float s_part[NW][4];
    __shared__ int   s_cfg[NA], s_lcfg[NA];
    __shared__ unsigned s_base;

    const int tid  = threadIdx.x;
    const int lane = tid & 31;
    const int wid  = tid >> 5;                         // 0..14
    const int bid  = blockIdx.x;
    const int u    = wid >> 1;                         // unit within block (compute warps)
    const int m    = wid & 1;                          // 0 = ih (x), 1 = hh (h)
    const int j    = bid * UPB + u;
    const bool active = (wid < 14) && (j < H);

    const bool leftw = (wid == 14) && ((bid & 3) == 0) && ((bid >> 2) < G);
    const int  leftr = bid >> 2;
    const bool ctxw  = (wid == 14) && ((bid & 7) == 0) && ((bid >> 3) < OP);
    const int  ctxr  = bid >> 3;
    const bool accW  = (bid == 1) && (wid == 14);      // acc = whole head warp of bid 1

    float ent = 0.f, lp = 0.f;                         // acc-warp registers

    // ---------------- prologue: fill SMEM weights (quantize fp32 -> biased u16) ----
    if (tid == 0) s_base = g_flags[bid];               // epoch for the final barrier
    if (tid < NA) { s_cfg[tid] = config[tid]; s_lcfg[tid] = left_config[tid]; }

    for (int idx = tid; idx < 2 * UPB * 2 * 4 * (H / 4); idx += NT) {
        int col = (idx & 255) * 4;                 // 256 float4 per row
        int t   = idx >> 8;
        int r   = t & 3;  t >>= 2;
        int mm  = t & 1;  t >>= 1;
        int k   = t % UPB;
        int l   = t / UPB;
        int jj  = bid * UPB + k;
        if (jj < H) {
            const float* src = (mm ? W_hh : W_ih) +
                               (size_t)l * 4 * H * H + ((size_t)r * H + jj) * H + col;
            float4 v = __ldcs((const float4*)src);
            ushort4 q;
            q.x = (unsigned short)(__float2int_rn(v.x * QSCALE) + 32768);
            q.y = (unsigned short)(__float2int_rn(v.y * QSCALE) + 32768);
            q.z = (unsigned short)(__float2int_rn(v.z * QSCALE) + 32768);
            q.w = (unsigned short)(__float2int_rn(v.w * QSCALE) + 32768);
            *(ushort4*)(w_s + ((((size_t)l * UPB + k) * 2 + mm) * 4 + r) * H + col) = q;
        }
    }

    // per-finalize-thread bias registers: bsr[l*4+g]
    const int jt = bid * UPB + tid;                    // unit for finalize thread tid<UPB
    const bool jt_ok = (tid < UPB) && (jt < H);
    float bsr[8];
    if (jt_ok) {
#pragma unroll
        for (int l = 0; l < 2; ++l)
#pragma unroll
            for (int g = 0; g < 4; ++g)
                bsr[l * 4 + g] = b_ih[l * 4 * H + g * H + jt] + b_hh[l * 4 * H + g * H + jt];
    }
    __syncthreads();
    unsigned bar = 0;                                  // counter-barrier index

    const unsigned short* wb0 = w_s + ((size_t)u * 2 + m) * 4 * H;       // layer 0
    const unsigned short* wb1 = wb0 + LAYER_STRIDE;                      // layer 1

#define DO_PHASE(WB, XV, HV, ZERO_H, CPRE, ZERO_C, HOUT, COUT, LIDX)            \
    do {                                                                        \
        float cpre_r = 0.f;                                                     \
        if (jt_ok && !(ZERO_C)) cpre_r = __ldcg(&(CPRE)[jt]);                   \
        if (active) {                                                           \
            float prt[4];                                                       \
            if (m == 0)            lstm_partial((WB), (XV), lane, prt);         \
            else if (ZERO_H)       { prt[0]=prt[1]=prt[2]=prt[3]=0.f; }         \
            else                   lstm_partial((WB), (HV), lane, prt);         \
            if (lane == 0) { s_part[wid][0]=prt[0]; s_part[wid][1]=prt[1];      \
                             s_part[wid][2]=prt[2]; s_part[wid][3]=prt[3]; }    \
        }                                                                       \
        HEADCODE;                                                               \
        __syncthreads();                                                        \
        if (jt_ok) {                                                            \
            float zi = (s_part[2*tid][0]+s_part[2*tid+1][0])*QINV + bsr[(LIDX)*4+0]; \
            float zf = (s_part[2*tid][1]+s_part[2*tid+1][1])*QINV + bsr[(LIDX)*4+1]; \
            float zg = (s_part[2*tid][2]+s_part[2*tid+1][2])*QINV + bsr[(LIDX)*4+2]; \
            float zo = (s_part[2*tid][3]+s_part[2*tid+1][3])*QINV + bsr[(LIDX)*4+3]; \
            float ii = 1.f/(1.f+expf(-zi));                                     \
            float ff = 1.f/(1.f+expf(-zf));                                     \
            float gg = tanhf(zg);                                               \
            float oo = 1.f/(1.f+expf(-zo));                                     \
            float cn = ff*cpre_r + ii*gg;                                       \
            __stcg(&(COUT)[jt], cn);                                            \
            __stcg(&(HOUT)[jt], oo*tanhf(cn));                                  \
        }                                                                       \
        grid_barrier(++bar);                                                    \
    } while (0)

    for (int a = 0; a < NA; ++a) {
        const int  q     = a & 1;
        const int  p     = q ^ 1;
        const bool first = (a == 0);
        const int  prevgap = first ? 0 : (s_cfg[a - 1] == 1);
        const int  sel   = prevgap;                    // state branch taken last step
        const bool gap   = (s_cfg[a] == 1);            // run gap phases this step?

        // ---- PHASE A: substep 0, layer 0 ------------------------------------------
        // head warp: if prev step had a gap -> left dots(a-1); else -> ctx dots(a-1)
#define HEADCODE                                                                \
        if (!first) {                                                           \
            if (prevgap) {                                                      \
                if (leftw) {                                                    \
                    float d = head_dot(left_W + ((size_t)(a-1) * G + leftr) * H,\
                                       g_h[p][1][1], lane);                     \
                    if (lane == 0) __stcg(&g_left_logits[leftr],                \
                                          d + left_b[(a-1)*G + leftr]);         \
                }                                                               \
            } else {                                                            \
                if (ctxw) {                                                     \
                    float d = head_dot(ctx_W + ((size_t)(a-1) * OP + ctxr) * H, \
                                       g_h[p][0][1], lane);                     \
                    if (lane == 0) __stcg(&g_ctx_logits[ctxr],                  \
                                          d + ctx_b[(a-1)*OP + ctxr]);          \
                }                                                               \
            }                                                                   \
        }
        DO_PHASE(wb0, (first ? g_emb : g_h[p][sel][1]), g_h[p][sel][0], first,
                 g_c[p][sel][0], first, g_h[q][0][0], g_c[q][0][0], 0);
#undef HEADCODE

        // ---- PHASE B: substep 0, layer 1 ------------------------------------------
        // acc warp: finish prev step's pending softmax (left if gap, else ctx)
#define HEADCODE                                                                \
        if (!first && accW) {                                                   \
            if (prevgap) warp_softmax_acc(g_left_logits, G, s_lcfg[a-1], lane,  \
                                          ent, lp);                             \
            else         warp_softmax_acc(g_ctx_logits, OP, s_cfg[a-1], lane,   \
                                          ent, lp);                             \
        }
        DO_PHASE(wb1, g_h[q][0][0], g_h[p][sel][1], first,
                 g_c[p][sel][1], first, g_h[q][0][1], g_c[q][0][1], 1);
#undef HEADCODE

        if (gap) {
            // ---- PHASE C: substep 1 (gap), layer 0; head warp: ctx dots(a) --------
#define HEADCODE                                                                \
            if (ctxw) {                                                         \
                float d = head_dot(ctx_W + ((size_t)a * OP + ctxr) * H,         \
                                   g_h[q][0][1], lane);                         \
                if (lane == 0) __stcg(&g_ctx_logits[ctxr],                      \
                                      d + ctx_b[a * OP + ctxr]);                \
            }
            DO_PHASE(wb0, g_h[q][0][1], g_h[q][0][0], false,
                     g_c[q][0][0], false, g_h[q][1][0], g_c[q][1][0], 0);
#undef HEADCODE

            // ---- PHASE D: substep 1 (gap), layer 1; acc warp: ctx softmax(a) ------
#define HEADCODE                                                                \
            if (accW) warp_softmax_acc(g_ctx_logits, OP, s_cfg[a], lane, ent, lp)
            DO_PHASE(wb1, g_h[q][1][0], g_h[q][0][1], false,
                     g_c[q][0][1], false, g_h[q][1][1], g_c[q][1][1], 1);
#undef HEADCODE
        }
        // if !gap: phases C/D contribute exactly 0 to ent/lp and leave state
        // untouched (mask mf == 0 in the reference) -> skipped entirely.
    }

    // ---- epilogue: pending head work for the final step (parity 1) ----------------
    {
        const int lastgap = (s_cfg[NA - 1] == 1);
        if (lastgap) {
            if (leftw) {
                float d = head_dot(left_W + ((size_t)(NA - 1) * G + leftr) * H,
                                   g_h[1][1][1], lane);
                if (lane == 0) __stcg(&g_left_logits[leftr],
                                      d + left_b[(NA - 1) * G + leftr]);
            }
        } else {
            if (ctxw) {
                float d = head_dot(ctx_W + ((size_t)(NA - 1) * OP + ctxr) * H,
                                   g_h[1][0][1], lane);
                if (lane == 0) __stcg(&g_ctx_logits[ctxr],
                                      d + ctx_b[(NA - 1) * OP + ctxr]);
            }
        }
        grid_barrier(++bar);
        if (accW) {
            if (lastgap) warp_softmax_acc(g_left_logits, G, s_lcfg[NA - 1], lane, ent, lp);
            else         warp_softmax_acc(g_ctx_logits, OP, s_cfg[NA - 1], lane, ent, lp);
            if (lane == 0) { out[0] = ent; out[1] = lp; }
        }
    }

    // ---- final: flags barrier, then reset the counter for the next launch ---------
    // After this barrier no block can still be polling g_count, so the reset by
    // block 0 cannot be observed by an in-flight poll of this launch.
    flags_barrier(s_base + 1, lane);
    if (bid == 0 && tid == 0)
        asm volatile("st.global.u32 [%0], 0;" :: "l"(&g_count) : "memory");
}

extern "C" void kernel_launch(void* const* d_in, const int* in_sizes, int n_in,
                              void* d_out, int out_size) {
    (void)in_sizes; (void)n_in; (void)out_size;
    const float* g_emb_p    = (const float*)d_in[0];
    const float* W_ih_p     = (const float*)d_in[1];
    const float* W_hh_p     = (const float*)d_in[2];
    const float* b_ih_p     = (const float*)d_in[3];
    const float* b_hh_p     = (const float*)d_in[4];
    const float* ctx_W_p    = (const float*)d_in[5];
    const float* ctx_b_p    = (const float*)d_in[6];
    const float* left_W_p   = (const float*)d_in[7];
    const float* left_b_p   = (const float*)d_in[8];
    const int*   config_p   = (const int*)d_in[9];
    const int*   left_cfg_p = (const int*)d_in[10];
    float* out = (float*)d_out;

    static int smem_set = 0;
    if (!smem_set) {
        cudaFuncSetAttribute(controller_kernel,
                             cudaFuncAttributeMaxDynamicSharedMemorySize, SMEM_DYN);
        smem_set = 1;
    }

    controller_kernel<<<NB, NT, SMEM_DYN>>>(g_emb_p, W_ih_p, W_hh_p, b_ih_p, b_hh_p,
                                            ctx_W_p, ctx_b_p, left_W_p, left_b_p,
                                            config_p, left_cfg_p, out);
}

// round 10
// speedup vs baseline: 6.9782x; 1.5071x over previous
#include <cuda_runtime.h>
#include <math.h>

#define H    1024
#define NA   128
#define OP   16
#define G    32
#define UPB  7            // hidden units per block
#define NB   147          // 147*7 = 1029 >= 1024; all co-resident (<=148 SMs)
#define NT   480          // 15 warps: 14 compute (2 per unit) + 1 head warp
#define NW   15
#define NREP 4            // h-vector replicas (spread L2 slices)

typedef unsigned long long ull;

#define QSCALE   327670.0f         // |w| < 0.1 -> |q| <= 32767
#define QINV     (1.0f / 327670.0f)
#define DEC_BIAS (-8421376.0f)     // -(8388608 + 32768)

#define LAYER_STRIDE (UPB * 2 * 4 * H)          // u16 elements per layer per block
#define SMEM_DYN     (2 * LAYER_STRIDE * 2)     // bytes: 229376

// ---------------- persistent device state (no allocations allowed) ----------------
// Step-versioned h buffers: every phase writes FRESH addresses -> plain L1-cached
// loads are coherence-safe (no stale copy can exist; L1 flushed per launch).
__device__ __align__(16) float g_hv[NA][2][2][NREP][H];   // 8 MB
__device__ float g_ctx_logits[OP];
__device__ float g_left_logits[G];
__device__ unsigned g_count;                      // barrier counter; 0 at launch start
__device__ unsigned g_flags[160];                 // per-block epochs (final barrier)

// ---------------- packed f32x2 helpers -------------------------------------------
__device__ __forceinline__ void fma2(ull& a, ull b, ull c) {
    asm("fma.rn.f32x2 %0, %1, %2, %0;" : "+l"(a) : "l"(b), "l"(c));
}
__device__ __forceinline__ ull pack2(float x, float y) {
    ull v; asm("mov.b64 %0, {%1, %2};" : "=l"(v) : "f"(x), "f"(y)); return v;
}
__device__ __forceinline__ float2 unpack2(ull v) {
    float2 f; asm("mov.b64 {%0, %1}, %2;" : "=f"(f.x), "=f"(f.y) : "l"(v)); return f;
}
// exact biased-u16 pair -> f32x2 of original int16 values (PRMT splice, no cvt)
__device__ __forceinline__ ull dec2(unsigned w, unsigned magic, ull bias2) {
    unsigned lo, hi;
    asm("prmt.b32 %0, %1, %2, 0x7410;" : "=r"(lo) : "r"(w), "r"(magic));
    asm("prmt.b32 %0, %1, %2, 0x7432;" : "=r"(hi) : "r"(w), "r"(magic));
    ull v;
    asm("mov.b64 %0, {%1, %2};" : "=l"(v) : "r"(lo), "r"(hi));
    asm("add.rn.f32x2 %0, %0, %1;" : "+l"(v) : "l"(bias2));
    return v;
}

__device__ __forceinline__ float warp_reduce(float v) {
#pragma unroll
    for (int o = 16; o; o >>= 1) v += __shfl_xor_sync(0xffffffffu, v, o);
    return v;
}
__device__ __forceinline__ float dot4(float4 a, float4 b) {
    return a.x * b.x + a.y * b.y + a.z * b.z + a.w * b.w;
}

// ---------------- single-counter grid barrier (1 RED + 1-word poll) ---------------
__device__ __forceinline__ void grid_barrier(unsigned k) {
    const unsigned target = k * (unsigned)NB;
    __syncthreads();
    if (threadIdx.x == 0) {
        asm volatile("red.release.gpu.global.add.u32 [%0], 1;"
                     :: "l"(&g_count) : "memory");
        unsigned v;
        do {
            asm volatile("ld.acquire.gpu.global.u32 %0, [%1];"
                         : "=r"(v) : "l"(&g_count) : "memory");
        } while ((int)(v - target) < 0);
    }
    __syncthreads();
}

// all-to-all flags barrier: used ONCE at kernel end to make the counter reset safe.
__device__ __forceinline__ void flags_barrier(unsigned target, int lane) {
    __syncthreads();
    if (threadIdx.x == 0)
        asm volatile("st.release.gpu.global.u32 [%0], %1;"
                     :: "l"(&g_flags[blockIdx.x]), "r"(target) : "memory");
    if (threadIdx.x < 32) {
        for (;;) {
            bool ok = true;
#pragma unroll
            for (int k = 0; k < 5; ++k) {
                int idx = k * 32 + lane;
                unsigned f;
                asm volatile("ld.acquire.gpu.global.u32 %0, [%1];"
                             : "=r"(f) : "l"(&g_flags[idx]) : "memory");
                ok &= (idx >= NB) | ((int)(f - target) >= 0);
            }
            if (__all_sync(0xffffffffu, ok)) break;
        }
    }
    __syncthreads();
}

// per-warp partial: 4 gate rows (u16, SMEM) . vec (fp32, global; L1-cacheable
// because vectors are step-versioned/fresh), 1024 cols.
__device__ __forceinline__ void lstm_partial(
    const unsigned short* wbase,            // SMEM: [4][1024] u16 rows
    const float* __restrict__ vec,          // global: 1024 floats (fresh lines)
    int lane, float p[4])
{
    const unsigned magic = 0x4B000000u;
    const ull bias2 = pack2(DEC_BIAS, DEC_BIAS);
    ull acc[4] = {0, 0, 0, 0};

#pragma unroll
    for (int k = 0; k < 4; ++k) {
        const int c16 = k * 32 + lane;                  // 16B chunk id (0..127)
        const float4* vp = (const float4*)vec + c16 * 2;
        float4 va = vp[0];                              // plain ld -> L1 MSHR dedup
        float4 vb = vp[1];
        ull v0 = pack2(va.x, va.y), v1 = pack2(va.z, va.w);
        ull v2 = pack2(vb.x, vb.y), v3 = pack2(vb.z, vb.w);
#pragma unroll
        for (int r = 0; r < 4; ++r) {
            uint4 w = ((const uint4*)(wbase + r * H))[c16];   // LDS.128
            fma2(acc[r], dec2(w.x, magic, bias2), v0);
            fma2(acc[r], dec2(w.y, magic, bias2), v1);
            fma2(acc[r], dec2(w.z, magic, bias2), v2);
            fma2(acc[r], dec2(w.w, magic, bias2), v3);
        }
    }
#pragma unroll
    for (int g = 0; g < 4; ++g) {
        float2 s = unpack2(acc[g]);
        p[g] = warp_reduce(s.x + s.y);
    }
}

// head row dot: fp32 weight row (global, streaming) . x (global, fresh lines)
__device__ __forceinline__ float head_dot(const float* __restrict__ w,
                                          const float* __restrict__ x, int lane) {
    const float4* wv = (const float4*)w;
    const float4* xv = (const float4*)x;
    float a = 0.f;
#pragma unroll
    for (int it = 0; it < 8; ++it) {
        int t = it * 32 + lane;
        a += dot4(__ldcs(wv + t), xv[t]);
    }
    return warp_reduce(a);
}

// warp-parallel log-softmax; accumulates into acc-warp registers (deterministic).
__device__ __forceinline__ void warp_softmax_acc(const float* __restrict__ logits,
                                                 int n, int chosen, int lane,
                                                 float& ent, float& lp) {
    float v = (lane < n) ? __ldcg(logits + lane) : -1e30f;
    float m = v;
#pragma unroll
    for (int o = 16; o; o >>= 1) m = fmaxf(m, __shfl_xor_sync(0xffffffffu, m, o));
    float e = (lane < n) ? expf(v - m) : 0.f;
    float se = e;
#pragma unroll
    for (int o = 16; o; o >>= 1) se += __shfl_xor_sync(0xffffffffu, se, o);
    float lse = m + logf(se);
    float ls = v - lse;
    float t = (lane < n) ? expf(ls) * ls : 0.f;
#pragma unroll
    for (int o = 16; o; o >>= 1) t += __shfl_xor_sync(0xffffffffu, t, o);
    float lsc = __shfl_sync(0xffffffffu, ls, chosen);
    ent += -t;
    lp  += lsc;
}

// ---------------- the single persistent kernel ------------------------------------
__global__ void __launch_bounds__(NT, 1)
controller_kernel(const float* __restrict__ g_emb,
                  const float* __restrict__ W_ih, const float* __restrict__ W_hh,
                  const float* __restrict__ b_ih, const float* __restrict__ b_hh,
                  const float* __restrict__ ctx_W, const float* __restrict__ ctx_b,
                  const float* __restrict__ left_W, const float* __restrict__ left_b,
                  const int* __restrict__ config, const int* __restrict__ left_config,
                  float* __restrict__ out)
{
    extern __shared__ unsigned short w_s[];           // [2][UPB][2][4][H] u16
    __shared__ float s_part[NW][4];
    __shared__ int   s_cfg[NA], s_lcfg[NA];
    __shared__ unsigned s_base;

    const int tid  = threadIdx.x;
    const int lane = tid & 31;
    const int wid  = tid >> 5;                         // 0..14
    const int bid  = blockIdx.x;
    const int rep  = bid & (NREP - 1);                 // read replica
    const int u    = wid >> 1;                         // unit within block
    const int m    = wid & 1;                          // 0 = ih (x), 1 = hh (h)
    const int j    = bid * UPB + u;
    const bool active = (wid < 14) && (j < H);

    const bool leftw = (wid == 14) && ((bid & 3) == 0) && ((bid >> 2) < G);
    const int  leftr = bid >> 2;
    const bool ctxw  = (wid == 14) && ((bid & 7) == 0) && ((bid >> 3) < OP);
    const int  ctxr  = bid >> 3;
    const bool accW  = (bid == 1) && (wid == 14);      // acc = head warp of bid 1

    float ent = 0.f, lp = 0.f;                         // acc-warp registers

#define HVP(A, S, L) (&g_hv[(A)][(S)][(L)][rep][0])
#define HVW(A, S, L) (&g_hv[(A)][(S)][(L)][0][0])

    // ---------------- prologue: fill SMEM weights (quantize fp32 -> biased u16) ----
    if (tid == 0) s_base = g_flags[bid];               // epoch for the final barrier
    if (tid < NA) { s_cfg[tid] = config[tid]; s_lcfg[tid] = left_config[tid]; }

    for (int idx = tid; idx < 2 * UPB * 2 * 4 * (H / 4); idx += NT) {
        int col = (idx & 255) * 4;                 // 256 float4 per row
        int t   = idx >> 8;
        int r   = t & 3;  t >>= 2;
        int mm  = t & 1;  t >>= 1;
        int k   = t % UPB;
        int l   = t / UPB;
        int jj  = bid * UPB + k;
        if (jj < H) {
            const float* src = (mm ? W_hh : W_ih) +
                               (size_t)l * 4 * H * H + ((size_t)r * H + jj) * H + col;
            float4 v = __ldcs((const float4*)src);
            ushort4 q;
            q.x = (unsigned short)(__float2int_rn(v.x * QSCALE) + 32768);
            q.y = (unsigned short)(__float2int_rn(v.y * QSCALE) + 32768);
            q.z = (unsigned short)(__float2int_rn(v.z * QSCALE) + 32768);
            q.w = (unsigned short)(__float2int_rn(v.w * QSCALE) + 32768);
            *(ushort4*)(w_s + ((((size_t)l * UPB + k) * 2 + mm) * 4 + r) * H + col) = q;
        }
    }

    // per-finalize-thread bias registers + cell-state registers (block-private!)
    const int jt = bid * UPB + tid;                    // unit for finalize thread tid<UPB
    const bool jt_ok = (tid < UPB) && (jt < H);
    float bsr[8];
    float c0 = 0.f, c1 = 0.f;                          // cell states, layers 0/1
    if (jt_ok) {
#pragma unroll
        for (int l = 0; l < 2; ++l)
#pragma unroll
            for (int g = 0; g < 4; ++g)
                bsr[l * 4 + g] = b_ih[l * 4 * H + g * H + jt] + b_hh[l * 4 * H + g * H + jt];
    }
    __syncthreads();
    unsigned bar = 0;                                  // counter-barrier index

    const unsigned short* wb0 = w_s + ((size_t)u * 2 + m) * 4 * H;       // layer 0
    const unsigned short* wb1 = wb0 + LAYER_STRIDE;                      // layer 1

#define DO_PHASE(WB, XV, HV, ZERO_H, CREG, ZERO_C, HOUT, LIDX)                  \
    do {                                                                        \
        if (active) {                                                           \
            float prt[4];                                                       \
            if (m == 0)            lstm_partial((WB), (XV), lane, prt);         \
            else if (ZERO_H)       { prt[0]=prt[1]=prt[2]=prt[3]=0.f; }         \
            else                   lstm_partial((WB), (HV), lane, prt);         \
            if (lane == 0) { s_part[wid][0]=prt[0]; s_part[wid][1]=prt[1];      \
                             s_part[wid][2]=prt[2]; s_part[wid][3]=prt[3]; }    \
        }                                                                       \
        HEADCODE;                                                               \
        __syncthreads();                                                        \
        if (jt_ok) {                                                            \
            float zi = (s_part[2*tid][0]+s_part[2*tid+1][0])*QINV + bsr[(LIDX)*4+0]; \
            float zf = (s_part[2*tid][1]+s_part[2*tid+1][1])*QINV + bsr[(LIDX)*4+1]; \
            float zg = (s_part[2*tid][2]+s_part[2*tid+1][2])*QINV + bsr[(LIDX)*4+2]; \
            float zo = (s_part[2*tid][3]+s_part[2*tid+1][3])*QINV + bsr[(LIDX)*4+3]; \
            float ii = 1.f/(1.f+expf(-zi));                                     \
            float ff = 1.f/(1.f+expf(-zf));                                     \
            float gg = tanhf(zg);                                               \
            float oo = 1.f/(1.f+expf(-zo));                                     \
            float cn = ff*((ZERO_C)?0.f:(CREG)) + ii*gg;                        \
            (CREG) = cn;                                                        \
            float hn = oo*tanhf(cn);                                            \
            float* hb = (HOUT);                                                 \
            _Pragma("unroll")                                                   \
            for (int r = 0; r < NREP; ++r) __stcg(hb + r * H + jt, hn);         \
        }                                                                       \
        grid_barrier(++bar);                                                    \
    } while (0)

    for (int a = 0; a < NA; ++a) {
        const bool first = (a == 0);
        const int  prevgap = first ? 0 : (s_cfg[a - 1] == 1);
        const int  sel   = prevgap;                    // state branch taken last step
        const bool gap   = (s_cfg[a] == 1);            // run gap phases this step?

        // ---- PHASE A: substep 0, layer 0 ------------------------------------------
#define HEADCODE                                                                \
        if (!first) {                                                           \
            if (prevgap) {                                                      \
                if (leftw) {                                                    \
                    float d = head_dot(left_W + ((size_t)(a-1) * G + leftr) * H,\
                                       HVP(a-1, 1, 1), lane);                   \
                    if (lane == 0) __stcg(&g_left_logits[leftr],                \
                                          d + left_b[(a-1)*G + leftr]);         \
                }                                                               \
            } else {                                                            \
                if (ctxw) {                                                     \
                    float d = head_dot(ctx_W + ((size_t)(a-1) * OP + ctxr) * H, \
                                       HVP(a-1, 0, 1), lane);                   \
                    if (lane == 0) __stcg(&g_ctx_logits[ctxr],                  \
                                          d + ctx_b[(a-1)*OP + ctxr]);          \
                }                                                               \
            }                                                                   \
        }
        DO_PHASE(wb0, (first ? g_emb : HVP(a-1, sel, 1)), HVP(a-1, sel, 0), first,
                 c0, first, HVW(a, 0, 0), 0);
#undef HEADCODE

        // ---- PHASE B: substep 0, layer 1 ------------------------------------------
#define HEADCODE                                                                \
        if (!first && accW) {                                                   \
            if (prevgap) warp_softmax_acc(g_left_logits, G, s_lcfg[a-1], lane,  \
                                          ent, lp);                             \
            else         warp_softmax_acc(g_ctx_logits, OP, s_cfg[a-1], lane,   \
                                          ent, lp);                             \
        }
        DO_PHASE(wb1, HVP(a, 0, 0), HVP(a-1, sel, 1), first,
                 c1, first, HVW(a, 0, 1), 1);
#undef HEADCODE

        if (gap) {
            // ---- PHASE C: substep 1 (gap), layer 0; head warp: ctx dots(a) --------
#define HEADCODE                                                                \
            if (ctxw) {                                                         \
                float d = head_dot(ctx_W + ((size_t)a * OP + ctxr) * H,         \
                                   HVP(a, 0, 1), lane);                         \
                if (lane == 0) __stcg(&g_ctx_logits[ctxr],                      \
                                      d + ctx_b[a * OP + ctxr]);                \
            }
            DO_PHASE(wb0, HVP(a, 0, 1), HVP(a, 0, 0), false,
                     c0, false, HVW(a, 1, 0), 0);
#undef HEADCODE

            // ---- PHASE D: substep 1 (gap), layer 1; acc warp: ctx softmax(a) ------
#define HEADCODE                                                                \
            if (accW) warp_softmax_acc(g_ctx_logits, OP, s_cfg[a], lane, ent, lp)
            DO_PHASE(wb1, HVP(a, 1, 0), HVP(a, 0, 1), false,
                     c1, false, HVW(a, 1, 1), 1);
#undef HEADCODE
        }
        // if !gap: phases C/D are exact no-ops (mask mf == 0) -> skipped; c0/c1
        // registers untouched == where(m, new, old) semantics.
    }

    // ---- epilogue: pending head work for the final step ---------------------------
    {
        const int lastgap = (s_cfg[NA - 1] == 1);
        if (lastgap) {
            if (leftw) {
                float d = head_dot(left_W + ((size_t)(NA - 1) * G + leftr) * H,
                                   HVP(NA-1, 1, 1), lane);
                if (lane == 0) __stcg(&g_left_logits[leftr],
                                      d + left_b[(NA - 1) * G + leftr]);
            }
        } else {
            if (ctxw) {
                float d = head_dot(ctx_W + ((size_t)(NA - 1) * OP + ctxr) * H,
                                   HVP(NA-1, 0, 1), lane);
                if (lane == 0) __stcg(&g_ctx_logits[ctxr],
                                      d + ctx_b[(NA - 1) * OP + ctxr]);
            }
        }
        grid_barrier(++bar);
        if (accW) {
            if (lastgap) warp_softmax_acc(g_left_logits, G, s_lcfg[NA - 1], lane, ent, lp);
            else         warp_softmax_acc(g_ctx_logits, OP, s_cfg[NA - 1], lane, ent, lp);
            if (lane == 0) { out[0] = ent; out[1] = lp; }
        }
    }

    // ---- final: flags barrier, then reset the counter for the next launch ---------
    flags_barrier(s_base + 1, lane);
    if (bid == 0 && tid == 0)
        asm volatile("st.global.u32 [%0], 0;" :: "l"(&g_count) : "memory");
#undef DO_PHASE
#undef HVP
#undef HVW
}

extern "C" void kernel_launch(void* const* d_in, const int* in_sizes, int n_in,
                              void* d_out, int out_size) {
    (void)in_sizes; (void)n_in; (void)out_size;
    const float* g_emb_p    = (const float*)d_in[0];
    const float* W_ih_p     = (const float*)d_in[1];
    const float* W_hh_p     = (const float*)d_in[2];
    const float* b_ih_p     = (const float*)d_in[3];
    const float* b_hh_p     = (const float*)d_in[4];
    const float* ctx_W_p    = (const float*)d_in[5];
    const float* ctx_b_p    = (const float*)d_in[6];
    const float* left_W_p   = (const float*)d_in[7];
    const float* left_b_p   = (const float*)d_in[8];
    const int*   config_p   = (const int*)d_in[9];
    const int*   left_cfg_p = (const int*)d_in[10];
    float* out = (float*)d_out;

    static int smem_set = 0;
    if (!smem_set) {
        cudaFuncSetAttribute(controller_kernel,
                             cudaFuncAttributeMaxDynamicSharedMemorySize, SMEM_DYN);
        smem_set = 1;
    }

    controller_kernel<<<NB, NT, SMEM_DYN>>>(g_emb_p, W_ih_p, W_hh_p, b_ih_p, b_hh_p,
                                            ctx_W_p, ctx_b_p, left_W_p, left_b_p,
                                            config_p, left_cfg_p, out);
}